// round 2
// baseline (speedup 1.0000x reference)
#include <cuda_runtime.h>
#include <math.h>

#define BB 16
#define T 4096
#define C 8
#define F 64
#define KW 11
#define PAD 5
#define L 4096

// scratch (device globals: no allocation allowed)
__device__ float g_h[BB * F * T];      // conv+bn out, then softmax+pe, layout [B][F][T]
__device__ float g_shift[BB * L];

// ---------------------------------------------------------------------------
// K1: Conv1D(SAME) + BatchNorm, output transposed to [B, F, T]
// block: 256 threads = 32 (t-pairs) x 8 (f-groups of 8); t-tile 64
// ---------------------------------------------------------------------------
#define CONV_TT 64
__global__ __launch_bounds__(256) void conv_bn_kernel(
    const float* __restrict__ x, const float* __restrict__ cw,
    const float* __restrict__ cb, const float* __restrict__ gamma,
    const float* __restrict__ beta, const float* __restrict__ mean,
    const float* __restrict__ var)
{
    __shared__ float xs[(CONV_TT + KW - 1) * 9];  // rows padded to 9 floats (bank-conflict-free)
    __shared__ float ws[KW * C * F];
    __shared__ float sc[F], bi[F];

    int b = blockIdx.y;
    int t0 = blockIdx.x * CONV_TT;
    int tid = threadIdx.x;

    for (int idx = tid; idx < (CONV_TT + KW - 1) * 9; idx += 256) {
        int i = idx / 9, c = idx % 9;
        float v = 0.f;
        int tg = t0 + i - PAD;
        if (c < 8 && tg >= 0 && tg < T) v = x[(b * T + tg) * C + c];
        xs[idx] = v;
    }
    for (int idx = tid; idx < KW * C * F; idx += 256) ws[idx] = cw[idx];
    if (tid < F) {
        float s = gamma[tid] / sqrtf(var[tid] + 1e-3f);
        sc[tid] = s;
        bi[tid] = (cb[tid] - mean[tid]) * s + beta[tid];
    }
    __syncthreads();

    int tx = tid & 31;   // t-pair
    int ty = tid >> 5;   // f-group
    float acc0[8], acc1[8];
#pragma unroll
    for (int j = 0; j < 8; j++) { acc0[j] = 0.f; acc1[j] = 0.f; }

#pragma unroll
    for (int k = 0; k < KW; k++) {
#pragma unroll
        for (int c = 0; c < C; c++) {
            float x0 = xs[(tx * 2 + k) * 9 + c];
            float x1 = xs[(tx * 2 + 1 + k) * 9 + c];
            const float* wrow = &ws[(k * C + c) * F + ty * 8];
#pragma unroll
            for (int j = 0; j < 8; j++) {
                float w = wrow[j];
                acc0[j] += x0 * w;
                acc1[j] += x1 * w;
            }
        }
    }
#pragma unroll
    for (int j = 0; j < 8; j++) {
        int f = ty * 8 + j;
        float s = sc[f], o = bi[f];
        float2 v;
        v.x = acc0[j] * s + o;
        v.y = acc1[j] * s + o;
        *(float2*)&g_h[(size_t)(b * F + f) * T + t0 + tx * 2] = v;
    }
}

// ---------------------------------------------------------------------------
// K2: softmax over T (contiguous row) + sine positional encoding, in-place
// one block per (b,f) row of 4096; 256 threads x 16 elements
// ---------------------------------------------------------------------------
__global__ __launch_bounds__(256) void softmax_pe_kernel()
{
    int r = blockIdx.x;          // b*F + f
    int f = r & (F - 1);
    float* row = g_h + (size_t)r * T;
    int tid = threadIdx.x;

    float v[16];
#pragma unroll
    for (int i = 0; i < 16; i++) v[i] = row[i * 256 + tid];

    float m = v[0];
#pragma unroll
    for (int i = 1; i < 16; i++) m = fmaxf(m, v[i]);

    __shared__ float sm[8], ss[8];
#pragma unroll
    for (int o = 16; o > 0; o >>= 1) m = fmaxf(m, __shfl_xor_sync(~0u, m, o));
    if ((tid & 31) == 0) sm[tid >> 5] = m;
    __syncthreads();
    m = sm[0];
#pragma unroll
    for (int w = 1; w < 8; w++) m = fmaxf(m, sm[w]);

    float e[16];
    float lsum = 0.f;
#pragma unroll
    for (int i = 0; i < 16; i++) { e[i] = expf(v[i] - m); lsum += e[i]; }
#pragma unroll
    for (int o = 16; o > 0; o >>= 1) lsum += __shfl_xor_sync(~0u, lsum, o);
    if ((tid & 31) == 0) ss[tid >> 5] = lsum;
    __syncthreads();
    float total = 0.f;
#pragma unroll
    for (int w = 0; w < 8; w++) total += ss[w];

    // sine position encoding (match reference: libdevice pow/sin/cos on fp32)
    float ts = powf(1e-4f, (float)(2 * (f >> 1)) / 64.0f);
    bool odd = (f & 1);
#pragma unroll
    for (int i = 0; i < 16; i++) {
        int t = i * 256 + tid;
        float ang = (float)t * ts;
        float pe = odd ? cosf(ang) : sinf(ang);
        row[i * 256 + tid] = e[i] / total + pe;
    }
}

// ---------------------------------------------------------------------------
// K3: fused Dense GEMM + sigmoid + sum over t -> shift[B, L]
// A = g_h[b] as [F=64][T] (K-major over f), W = dense_w [64][L]
// block tile: 64 t x 128 l, K=64 full; 256 threads, micro 4t x 8l
// ---------------------------------------------------------------------------
#define GT 64
#define GL 128
__global__ __launch_bounds__(256) void gemm_sig_kernel(
    const float* __restrict__ dw, const float* __restrict__ db)
{
    __shared__ float Ws[F * GL];  // 32 KB
    __shared__ float As[F * GT];  // 16 KB

    int b = blockIdx.y;
    int l0 = blockIdx.x * GL;
    int tid = threadIdx.x;
    int tx = tid & 15;   // l
    int ty = tid >> 4;   // t

    // load W tile once: [f][l0..l0+127]
    {
        const float4* dw4 = (const float4*)dw;
        float4* Ws4 = (float4*)Ws;
#pragma unroll
        for (int it = 0; it < 8; it++) {
            int e = tid + it * 256;           // 2048 float4s
            int f = e >> 5, j4 = e & 31;
            Ws4[f * 32 + j4] = dw4[f * (L / 4) + (l0 >> 2) + j4];
        }
    }

    float breg[8];
#pragma unroll
    for (int j = 0; j < 8; j++) breg[j] = db[l0 + tx * 8 + j];

    float dacc[8];
#pragma unroll
    for (int j = 0; j < 8; j++) dacc[j] = 0.f;

    const float4* a4base = (const float4*)(g_h + (size_t)b * F * T);

    for (int t0 = 0; t0 < T; t0 += GT) {
        // load A tile [f][t0..t0+63]
        {
            float4* As4 = (float4*)As;
#pragma unroll
            for (int it = 0; it < 4; it++) {
                int e = tid + it * 256;       // 1024 float4s
                int f = e >> 4, j4 = e & 15;
                As4[f * 16 + j4] = a4base[f * (T / 4) + (t0 >> 2) + j4];
            }
        }
        __syncthreads();

        float acc[4][8];
#pragma unroll
        for (int i = 0; i < 4; i++)
#pragma unroll
            for (int j = 0; j < 8; j++) acc[i][j] = 0.f;

#pragma unroll 8
        for (int f = 0; f < F; f++) {
            float4 av = *(const float4*)&As[f * GT + ty * 4];
            float4 w0 = *(const float4*)&Ws[f * GL + tx * 8];
            float4 w1 = *(const float4*)&Ws[f * GL + tx * 8 + 4];
            float aa[4] = {av.x, av.y, av.z, av.w};
            float wv[8] = {w0.x, w0.y, w0.z, w0.w, w1.x, w1.y, w1.z, w1.w};
#pragma unroll
            for (int i = 0; i < 4; i++)
#pragma unroll
                for (int j = 0; j < 8; j++) acc[i][j] += aa[i] * wv[j];
        }

        // sigmoid epilogue: d = 2*sigmoid(z)-1 = (1-e^-z)/(1+e^-z), sum over t
#pragma unroll
        for (int i = 0; i < 4; i++) {
#pragma unroll
            for (int j = 0; j < 8; j++) {
                float z = acc[i][j] + breg[j];
                z = fminf(fmaxf(z, -30.f), 30.f);
                float eZ = __expf(-z);
                dacc[j] += (1.f - eZ) / (1.f + eZ);
            }
        }
        __syncthreads();
    }

    // reduce dacc over the 16 ty rows (reuse As as scratch: need 2048 floats)
    float* red = As;
#pragma unroll
    for (int j = 0; j < 8; j++) red[ty * GL + tx * 8 + j] = dacc[j];
    __syncthreads();
    if (tid < GL) {
        float s = 0.f;
#pragma unroll
        for (int r = 0; r < 16; r++) s += red[r * GL + tid];
        g_shift[b * L + l0 + tid] = s;
    }
}

// ---------------------------------------------------------------------------
// K4: Gaussian RBF warp — out[b,l,:] = sum_t exp(-(t+1 - s)^2)/AMP * x[b,t,:]
// window truncated to |d| <= 6 (exp(-36) ~ 2e-16, far below fp32 noise)
// ---------------------------------------------------------------------------
__global__ __launch_bounds__(256) void warp_kernel(
    const float* __restrict__ x, float* __restrict__ out)
{
    int gid = blockIdx.x * 256 + threadIdx.x;   // = b*L + l
    int b = gid >> 12;
    int l = gid & (L - 1);
    float scale = (float)T / (float)L;
    float s = ((float)(l + 1) + g_shift[gid]) * scale;

    const float INV_AMP = (float)(1.0 / 1.772637204826652);
    float acc[8];
#pragma unroll
    for (int c = 0; c < 8; c++) acc[c] = 0.f;

    int lo = (int)ceilf(s - 6.0f);  if (lo < 1) lo = 1;
    int hi = (int)floorf(s + 6.0f); if (hi > T) hi = T;

    const float* xb = x + (size_t)b * T * C;
    for (int t = lo; t <= hi; t++) {
        float dd = (float)t - s;
        float wgt = expf(-dd * dd) * INV_AMP;
        const float4* xr = (const float4*)&xb[(t - 1) * C];
        float4 p0 = xr[0], p1 = xr[1];
        acc[0] += wgt * p0.x; acc[1] += wgt * p0.y;
        acc[2] += wgt * p0.z; acc[3] += wgt * p0.w;
        acc[4] += wgt * p1.x; acc[5] += wgt * p1.y;
        acc[6] += wgt * p1.z; acc[7] += wgt * p1.w;
    }
    float4* o = (float4*)&out[(size_t)gid * C];
    float4 r0 = {acc[0], acc[1], acc[2], acc[3]};
    float4 r1 = {acc[4], acc[5], acc[6], acc[7]};
    o[0] = r0; o[1] = r1;
}

// ---------------------------------------------------------------------------
extern "C" void kernel_launch(void* const* d_in, const int* in_sizes, int n_in,
                              void* d_out, int out_size)
{
    const float* x     = (const float*)d_in[0];
    const float* cw    = (const float*)d_in[1];
    const float* cb    = (const float*)d_in[2];
    const float* gamma = (const float*)d_in[3];
    const float* beta  = (const float*)d_in[4];
    const float* mean  = (const float*)d_in[5];
    const float* var   = (const float*)d_in[6];
    const float* dw    = (const float*)d_in[7];
    const float* db    = (const float*)d_in[8];
    float* out = (float*)d_out;

    conv_bn_kernel<<<dim3(T / CONV_TT, BB), 256>>>(x, cw, cb, gamma, beta, mean, var);
    softmax_pe_kernel<<<BB * F, 256>>>();
    gemm_sig_kernel<<<dim3(L / GL, BB), 256>>>(dw, db);
    warp_kernel<<<(BB * L) / 256, 256>>>(x, out);
}

// round 3
// speedup vs baseline: 1.1192x; 1.1192x over previous
#include <cuda_runtime.h>
#include <math.h>

#define BB 16
#define T 4096
#define C 8
#define F 64
#define KW 11
#define PAD 5
#define L 4096
#define SPLIT 4

// scratch (device globals: no allocation allowed)
__device__ float g_h[BB * F * T];                 // conv+bn out, then softmax+pe, [B][F][T]
__device__ float g_part[SPLIT * BB * L];          // split-T partial shift sums

// ---------------------------------------------------------------------------
// K1: Conv1D(SAME) + BatchNorm, output transposed to [B, F, T]
// ---------------------------------------------------------------------------
#define CONV_TT 64
__global__ __launch_bounds__(256) void conv_bn_kernel(
    const float* __restrict__ x, const float* __restrict__ cw,
    const float* __restrict__ cb, const float* __restrict__ gamma,
    const float* __restrict__ beta, const float* __restrict__ mean,
    const float* __restrict__ var)
{
    __shared__ float xs[(CONV_TT + KW - 1) * 9];
    __shared__ float ws[KW * C * F];
    __shared__ float sc[F], bi[F];

    int b = blockIdx.y;
    int t0 = blockIdx.x * CONV_TT;
    int tid = threadIdx.x;

    for (int idx = tid; idx < (CONV_TT + KW - 1) * 9; idx += 256) {
        int i = idx / 9, c = idx % 9;
        float v = 0.f;
        int tg = t0 + i - PAD;
        if (c < 8 && tg >= 0 && tg < T) v = x[(b * T + tg) * C + c];
        xs[idx] = v;
    }
    for (int idx = tid; idx < KW * C * F; idx += 256) ws[idx] = cw[idx];
    if (tid < F) {
        float s = gamma[tid] / sqrtf(var[tid] + 1e-3f);
        sc[tid] = s;
        bi[tid] = (cb[tid] - mean[tid]) * s + beta[tid];
    }
    __syncthreads();

    int tx = tid & 31;
    int ty = tid >> 5;
    float acc0[8], acc1[8];
#pragma unroll
    for (int j = 0; j < 8; j++) { acc0[j] = 0.f; acc1[j] = 0.f; }

#pragma unroll
    for (int k = 0; k < KW; k++) {
#pragma unroll
        for (int c = 0; c < C; c++) {
            float x0 = xs[(tx * 2 + k) * 9 + c];
            float x1 = xs[(tx * 2 + 1 + k) * 9 + c];
            const float* wrow = &ws[(k * C + c) * F + ty * 8];
#pragma unroll
            for (int j = 0; j < 8; j++) {
                float w = wrow[j];
                acc0[j] += x0 * w;
                acc1[j] += x1 * w;
            }
        }
    }
#pragma unroll
    for (int j = 0; j < 8; j++) {
        int f = ty * 8 + j;
        float s = sc[f], o = bi[f];
        float2 v;
        v.x = acc0[j] * s + o;
        v.y = acc1[j] * s + o;
        *(float2*)&g_h[(size_t)(b * F + f) * T + t0 + tx * 2] = v;
    }
}

// ---------------------------------------------------------------------------
// K2: softmax over T + sine positional encoding, in-place
// ---------------------------------------------------------------------------
__global__ __launch_bounds__(256) void softmax_pe_kernel()
{
    int r = blockIdx.x;
    int f = r & (F - 1);
    float* row = g_h + (size_t)r * T;
    int tid = threadIdx.x;

    float v[16];
#pragma unroll
    for (int i = 0; i < 16; i++) v[i] = row[i * 256 + tid];

    float m = v[0];
#pragma unroll
    for (int i = 1; i < 16; i++) m = fmaxf(m, v[i]);

    __shared__ float sm[8], ss[8];
#pragma unroll
    for (int o = 16; o > 0; o >>= 1) m = fmaxf(m, __shfl_xor_sync(~0u, m, o));
    if ((tid & 31) == 0) sm[tid >> 5] = m;
    __syncthreads();
    m = sm[0];
#pragma unroll
    for (int w = 1; w < 8; w++) m = fmaxf(m, sm[w]);

    float e[16];
    float lsum = 0.f;
#pragma unroll
    for (int i = 0; i < 16; i++) { e[i] = expf(v[i] - m); lsum += e[i]; }
#pragma unroll
    for (int o = 16; o > 0; o >>= 1) lsum += __shfl_xor_sync(~0u, lsum, o);
    if ((tid & 31) == 0) ss[tid >> 5] = lsum;
    __syncthreads();
    float total = 0.f;
#pragma unroll
    for (int w = 0; w < 8; w++) total += ss[w];

    float ts = powf(1e-4f, (float)(2 * (f >> 1)) / 64.0f);
    bool odd = (f & 1);
#pragma unroll
    for (int i = 0; i < 16; i++) {
        int t = i * 256 + tid;
        float ang = (float)t * ts;
        float pe = odd ? cosf(ang) : sinf(ang);
        row[i * 256 + tid] = e[i] / total + pe;
    }
}

// ---------------------------------------------------------------------------
// K3: fused Dense GEMM (packed f32x2 FFMA2) + sigmoid + partial t-sum
// block tile: 64 t x 128 l; split-T by 4; 256 threads; micro 4t x 8l (4 l-pairs)
// ---------------------------------------------------------------------------
#define GT 64
#define GL 128

#define FFMA2(acc, a, b) \
    asm("fma.rn.f32x2 %0, %1, %2, %0;" : "+l"(acc) : "l"(a), "l"(b))

__global__ __launch_bounds__(256) void gemm_sig_kernel(
    const float* __restrict__ dw, const float* __restrict__ db)
{
    __shared__ __align__(16) unsigned long long As2[F * GT];       // {a,a} pairs, 32KB
    __shared__ __align__(16) unsigned long long Ws2[F * (GL / 2)]; // {w_l,w_l+1}, 32KB

    int b = blockIdx.y;
    int l0 = blockIdx.x * GL;
    int z = blockIdx.z;
    int tid = threadIdx.x;
    int tx = tid & 15;   // l-group (8 l = 4 pairs)
    int ty = tid >> 4;   // t-group (4 t)

    // load W tile once: [f][l0..l0+127] (pairs are naturally contiguous)
    {
        const float4* dw4 = (const float4*)dw;
        float4* Ws4 = (float4*)Ws2;
#pragma unroll
        for (int it = 0; it < 8; it++) {
            int e = tid + it * 256;           // 2048 float4s
            int f = e >> 5, j4 = e & 31;
            Ws4[f * 32 + j4] = dw4[f * (L / 4) + (l0 >> 2) + j4];
        }
    }

    float breg[8];
#pragma unroll
    for (int j = 0; j < 8; j++) breg[j] = db[l0 + tx * 8 + j];

    float dacc[8];
#pragma unroll
    for (int j = 0; j < 8; j++) dacc[j] = 0.f;

    const float4* a4base = (const float4*)(g_h + (size_t)b * F * T);
    int tbeg = z * (T / SPLIT);
    int tend = tbeg + (T / SPLIT);

    for (int t0 = tbeg; t0 < tend; t0 += GT) {
        // load A tile [f][t0..t0+63] duplicated into {a,a} pairs
        {
            float2* As2f = (float2*)As2;
#pragma unroll
            for (int it = 0; it < 4; it++) {
                int e = tid + it * 256;       // 1024 float4s
                int f = e >> 4, j4 = e & 15;
                float4 v = a4base[f * (T / 4) + (t0 >> 2) + j4];
                As2f[f * GT + j4 * 4 + 0] = make_float2(v.x, v.x);
                As2f[f * GT + j4 * 4 + 1] = make_float2(v.y, v.y);
                As2f[f * GT + j4 * 4 + 2] = make_float2(v.z, v.z);
                As2f[f * GT + j4 * 4 + 3] = make_float2(v.w, v.w);
            }
        }
        __syncthreads();

        unsigned long long acc[4][4];
#pragma unroll
        for (int i = 0; i < 4; i++)
#pragma unroll
            for (int j = 0; j < 4; j++) acc[i][j] = 0ull;  // bits zero = {0.f,0.f}

#pragma unroll 16
        for (int f = 0; f < F; f++) {
            ulonglong2 a01 = *(const ulonglong2*)&As2[f * GT + ty * 4];
            ulonglong2 a23 = *(const ulonglong2*)&As2[f * GT + ty * 4 + 2];
            ulonglong2 w01 = *(const ulonglong2*)&Ws2[f * (GL / 2) + tx * 4];
            ulonglong2 w23 = *(const ulonglong2*)&Ws2[f * (GL / 2) + tx * 4 + 2];
            unsigned long long a[4] = {a01.x, a01.y, a23.x, a23.y};
            unsigned long long w[4] = {w01.x, w01.y, w23.x, w23.y};
#pragma unroll
            for (int i = 0; i < 4; i++)
#pragma unroll
                for (int j = 0; j < 4; j++) FFMA2(acc[i][j], a[i], w[j]);
        }

        // sigmoid epilogue: d = 2*sigmoid(z)-1 = (1-e^-z)/(1+e^-z), sum over t
#pragma unroll
        for (int i = 0; i < 4; i++) {
#pragma unroll
            for (int j = 0; j < 4; j++) {
                float2 v = *(float2*)&acc[i][j];
                float z0 = fminf(fmaxf(v.x + breg[2 * j], -30.f), 30.f);
                float z1 = fminf(fmaxf(v.y + breg[2 * j + 1], -30.f), 30.f);
                float e0 = __expf(-z0);
                float e1 = __expf(-z1);
                dacc[2 * j]     += __fdividef(1.f - e0, 1.f + e0);
                dacc[2 * j + 1] += __fdividef(1.f - e1, 1.f + e1);
            }
        }
        __syncthreads();
    }

    // reduce dacc over the 16 ty rows (reuse As2 as scratch: 2048 floats)
    float* red = (float*)As2;
#pragma unroll
    for (int j = 0; j < 8; j++) red[ty * GL + tx * 8 + j] = dacc[j];
    __syncthreads();
    if (tid < GL) {
        float s = 0.f;
#pragma unroll
        for (int r = 0; r < 16; r++) s += red[r * GL + tid];
        g_part[((size_t)z * BB + b) * L + l0 + tid] = s;
    }
}

// ---------------------------------------------------------------------------
// K4: Gaussian RBF warp — combines split partials, truncated window |d| <= 6
// ---------------------------------------------------------------------------
__global__ __launch_bounds__(256) void warp_kernel(
    const float* __restrict__ x, float* __restrict__ out)
{
    int gid = blockIdx.x * 256 + threadIdx.x;   // = b*L + l
    int b = gid >> 12;
    int l = gid & (L - 1);

    float shift = 0.f;
#pragma unroll
    for (int zz = 0; zz < SPLIT; zz++) shift += g_part[(size_t)zz * BB * L + gid];

    float scale = (float)T / (float)L;
    float s = ((float)(l + 1) + shift) * scale;

    const float INV_AMP = (float)(1.0 / 1.772637204826652);
    float acc[8];
#pragma unroll
    for (int c = 0; c < 8; c++) acc[c] = 0.f;

    int lo = (int)ceilf(s - 6.0f);  if (lo < 1) lo = 1;
    int hi = (int)floorf(s + 6.0f); if (hi > T) hi = T;

    const float* xb = x + (size_t)b * T * C;
    for (int t = lo; t <= hi; t++) {
        float dd = (float)t - s;
        float wgt = expf(-dd * dd) * INV_AMP;
        const float4* xr = (const float4*)&xb[(t - 1) * C];
        float4 p0 = xr[0], p1 = xr[1];
        acc[0] += wgt * p0.x; acc[1] += wgt * p0.y;
        acc[2] += wgt * p0.z; acc[3] += wgt * p0.w;
        acc[4] += wgt * p1.x; acc[5] += wgt * p1.y;
        acc[6] += wgt * p1.z; acc[7] += wgt * p1.w;
    }
    float4* o = (float4*)&out[(size_t)gid * C];
    float4 r0 = {acc[0], acc[1], acc[2], acc[3]};
    float4 r1 = {acc[4], acc[5], acc[6], acc[7]};
    o[0] = r0; o[1] = r1;
}

// ---------------------------------------------------------------------------
extern "C" void kernel_launch(void* const* d_in, const int* in_sizes, int n_in,
                              void* d_out, int out_size)
{
    const float* x     = (const float*)d_in[0];
    const float* cw    = (const float*)d_in[1];
    const float* cb    = (const float*)d_in[2];
    const float* gamma = (const float*)d_in[3];
    const float* beta  = (const float*)d_in[4];
    const float* mean  = (const float*)d_in[5];
    const float* var   = (const float*)d_in[6];
    const float* dw    = (const float*)d_in[7];
    const float* db    = (const float*)d_in[8];
    float* out = (float*)d_out;

    conv_bn_kernel<<<dim3(T / CONV_TT, BB), 256>>>(x, cw, cb, gamma, beta, mean, var);
    softmax_pe_kernel<<<BB * F, 256>>>();
    gemm_sig_kernel<<<dim3(L / GL, BB, SPLIT), 256>>>(dw, db);
    warp_kernel<<<(BB * L) / 256, 256>>>(x, out);
}

// round 4
// speedup vs baseline: 1.9683x; 1.7586x over previous
#include <cuda_runtime.h>
#include <math.h>

#define BB 16
#define T 4096
#define C 8
#define F 64
#define KW 11
#define PAD 5
#define L 4096
#define SPLIT 8

// scratch (device globals: no allocation allowed)
__device__ float g_h[BB * F * T];                 // conv+bn out, then softmax+pe, [B][F][T]
__device__ float g_part[SPLIT * BB * L];          // split-T partial shift sums

// ---------------------------------------------------------------------------
// K1: Conv1D(SAME) + BatchNorm, output transposed to [B, F, T]
// ---------------------------------------------------------------------------
#define CONV_TT 64
__global__ __launch_bounds__(256) void conv_bn_kernel(
    const float* __restrict__ x, const float* __restrict__ cw,
    const float* __restrict__ cb, const float* __restrict__ gamma,
    const float* __restrict__ beta, const float* __restrict__ mean,
    const float* __restrict__ var)
{
    __shared__ float xs[(CONV_TT + KW - 1) * 9];
    __shared__ float ws[KW * C * F];
    __shared__ float sc[F], bi[F];

    int b = blockIdx.y;
    int t0 = blockIdx.x * CONV_TT;
    int tid = threadIdx.x;

    for (int idx = tid; idx < (CONV_TT + KW - 1) * 9; idx += 256) {
        int i = idx / 9, c = idx % 9;
        float v = 0.f;
        int tg = t0 + i - PAD;
        if (c < 8 && tg >= 0 && tg < T) v = x[(b * T + tg) * C + c];
        xs[idx] = v;
    }
    for (int idx = tid; idx < KW * C * F; idx += 256) ws[idx] = cw[idx];
    if (tid < F) {
        float s = gamma[tid] / sqrtf(var[tid] + 1e-3f);
        sc[tid] = s;
        bi[tid] = (cb[tid] - mean[tid]) * s + beta[tid];
    }
    __syncthreads();

    int tx = tid & 31;
    int ty = tid >> 5;
    float acc0[8], acc1[8];
#pragma unroll
    for (int j = 0; j < 8; j++) { acc0[j] = 0.f; acc1[j] = 0.f; }

#pragma unroll
    for (int k = 0; k < KW; k++) {
#pragma unroll
        for (int c = 0; c < C; c++) {
            float x0 = xs[(tx * 2 + k) * 9 + c];
            float x1 = xs[(tx * 2 + 1 + k) * 9 + c];
            const float* wrow = &ws[(k * C + c) * F + ty * 8];
#pragma unroll
            for (int j = 0; j < 8; j++) {
                float w = wrow[j];
                acc0[j] += x0 * w;
                acc1[j] += x1 * w;
            }
        }
    }
#pragma unroll
    for (int j = 0; j < 8; j++) {
        int f = ty * 8 + j;
        float s = sc[f], o = bi[f];
        float2 v;
        v.x = acc0[j] * s + o;
        v.y = acc1[j] * s + o;
        *(float2*)&g_h[(size_t)(b * F + f) * T + t0 + tx * 2] = v;
    }
}

// ---------------------------------------------------------------------------
// K2: softmax over T + sine positional encoding, in-place
// ---------------------------------------------------------------------------
__global__ __launch_bounds__(256) void softmax_pe_kernel()
{
    int r = blockIdx.x;
    int f = r & (F - 1);
    float* row = g_h + (size_t)r * T;
    int tid = threadIdx.x;

    float v[16];
#pragma unroll
    for (int i = 0; i < 16; i++) v[i] = row[i * 256 + tid];

    float m = v[0];
#pragma unroll
    for (int i = 1; i < 16; i++) m = fmaxf(m, v[i]);

    __shared__ float sm[8], ss[8];
#pragma unroll
    for (int o = 16; o > 0; o >>= 1) m = fmaxf(m, __shfl_xor_sync(~0u, m, o));
    if ((tid & 31) == 0) sm[tid >> 5] = m;
    __syncthreads();
    m = sm[0];
#pragma unroll
    for (int w = 1; w < 8; w++) m = fmaxf(m, sm[w]);

    float e[16];
    float lsum = 0.f;
#pragma unroll
    for (int i = 0; i < 16; i++) { e[i] = expf(v[i] - m); lsum += e[i]; }
#pragma unroll
    for (int o = 16; o > 0; o >>= 1) lsum += __shfl_xor_sync(~0u, lsum, o);
    if ((tid & 31) == 0) ss[tid >> 5] = lsum;
    __syncthreads();
    float total = 0.f;
#pragma unroll
    for (int w = 0; w < 8; w++) total += ss[w];

    float ts = powf(1e-4f, (float)(2 * (f >> 1)) / 64.0f);
    bool odd = (f & 1);
#pragma unroll
    for (int i = 0; i < 16; i++) {
        int t = i * 256 + tid;
        float ang = (float)t * ts;
        float pe = odd ? cosf(ang) : sinf(ang);
        row[i * 256 + tid] = e[i] / total + pe;
    }
}

// ---------------------------------------------------------------------------
// K3: fused Dense GEMM (FFMA2) + sigmoid + partial t-sum
// block tile: 64 t x 256 l; 256 threads = 8 warps
// warp owns t-group (8 t, broadcast A), lane owns 8 l (4 FFMA2 pairs)
// W in smem as ull [F][4][32] (pair-major, lane-minor: conflict-free LDS.64)
// A in smem plain float [F][64]; {a,a} pairs built in registers (ALU pipe)
// ---------------------------------------------------------------------------
#define GT 64
#define GL 256

#define FFMA2(acc, a, b) \
    asm("fma.rn.f32x2 %0, %1, %2, %0;" : "+l"(acc) : "l"(a), "l"(b))

__device__ __forceinline__ unsigned long long dup2(float a) {
    unsigned long long r;
    unsigned int u = __float_as_uint(a);
    asm("mov.b64 %0, {%1, %1};" : "=l"(r) : "r"(u));
    return r;
}

extern __shared__ __align__(16) unsigned char g_smem[];

__global__ __launch_bounds__(256, 2) void gemm_sig_kernel(
    const float* __restrict__ dw, const float* __restrict__ db)
{
    unsigned long long* Ws = (unsigned long long*)g_smem;          // F*4*32 ull = 64KB
    float* As = (float*)(g_smem + F * 4 * 32 * 8);                 // F*64 floats = 16KB

    int b = blockIdx.y;
    int l0 = blockIdx.x * GL;
    int z = blockIdx.z;
    int tid = threadIdx.x;
    int lane = tid & 31;
    int wy = tid >> 5;

    // ---- load W tile once: [f][l0..l0+255] -> Ws[f][pair][lane] ----
#pragma unroll
    for (int it = 0; it < 16; it++) {
        int e = tid + it * 256;            // 0..4095 float4s
        int f = e >> 6, j4 = e & 63;
        float4 v = *(const float4*)(dw + (size_t)f * L + l0 + j4 * 4);
        int lw = j4 >> 1;
        int pb = (j4 & 1) * 2;
        unsigned long long u0 = (unsigned long long)__float_as_uint(v.x) |
                                ((unsigned long long)__float_as_uint(v.y) << 32);
        unsigned long long u1 = (unsigned long long)__float_as_uint(v.z) |
                                ((unsigned long long)__float_as_uint(v.w) << 32);
        Ws[f * 128 + pb * 32 + lw] = u0;
        Ws[f * 128 + (pb + 1) * 32 + lw] = u1;
    }

    float breg[8];
#pragma unroll
    for (int j = 0; j < 8; j++) breg[j] = db[l0 + lane * 8 + j];

    float dacc[8];
#pragma unroll
    for (int j = 0; j < 8; j++) dacc[j] = 0.f;

    const float4* a4base = (const float4*)(g_h + (size_t)b * F * T);
    float4* As4 = (float4*)As;
    int tbeg = z * (T / SPLIT);
    int tend = tbeg + (T / SPLIT);

    for (int t0 = tbeg; t0 < tend; t0 += GT) {
        __syncthreads();   // guard As against previous iteration readers
        // load A tile [f][t0..t0+63]
#pragma unroll
        for (int it = 0; it < 4; it++) {
            int e = tid + it * 256;        // 1024 float4s
            int f = e >> 4, j4 = e & 15;
            As4[f * 16 + j4] = a4base[f * (T / 4) + (t0 >> 2) + j4];
        }
        __syncthreads();

        unsigned long long acc[8][4];
#pragma unroll
        for (int i = 0; i < 8; i++)
#pragma unroll
            for (int p = 0; p < 4; p++) acc[i][p] = 0ull;

#pragma unroll 4
        for (int f = 0; f < F; f++) {
            float4 a03 = As4[f * 16 + wy * 2];       // broadcast across warp
            float4 a47 = As4[f * 16 + wy * 2 + 1];
            unsigned long long ad[8];
            ad[0] = dup2(a03.x); ad[1] = dup2(a03.y);
            ad[2] = dup2(a03.z); ad[3] = dup2(a03.w);
            ad[4] = dup2(a47.x); ad[5] = dup2(a47.y);
            ad[6] = dup2(a47.z); ad[7] = dup2(a47.w);
            unsigned long long w[4];
#pragma unroll
            for (int p = 0; p < 4; p++) w[p] = Ws[f * 128 + p * 32 + lane];
#pragma unroll
            for (int i = 0; i < 8; i++)
#pragma unroll
                for (int p = 0; p < 4; p++) FFMA2(acc[i][p], ad[i], w[p]);
        }

        // sigmoid epilogue: d = 2*sigmoid(z)-1 = (1-e^-z)/(1+e^-z), sum over t
#pragma unroll
        for (int i = 0; i < 8; i++) {
#pragma unroll
            for (int p = 0; p < 4; p++) {
                float2 v = *(float2*)&acc[i][p];
                float z0 = fminf(fmaxf(v.x + breg[2 * p], -30.f), 30.f);
                float z1 = fminf(fmaxf(v.y + breg[2 * p + 1], -30.f), 30.f);
                float e0 = __expf(-z0);
                float e1 = __expf(-z1);
                dacc[2 * p]     += __fdividef(1.f - e0, 1.f + e0);
                dacc[2 * p + 1] += __fdividef(1.f - e1, 1.f + e1);
            }
        }
    }

    // reduce dacc over the 8 warps (reuse As area: 8*256 floats = 8KB)
    __syncthreads();
    float* red = As;
#pragma unroll
    for (int j = 0; j < 8; j++) red[wy * GL + lane * 8 + j] = dacc[j];
    __syncthreads();
    {
        float s = 0.f;
#pragma unroll
        for (int r = 0; r < 8; r++) s += red[r * GL + tid];
        g_part[((size_t)z * BB + b) * L + l0 + tid] = s;
    }
}

// ---------------------------------------------------------------------------
// K4: Gaussian RBF warp — combines split partials, truncated window |d| <= 6
// ---------------------------------------------------------------------------
__global__ __launch_bounds__(256) void warp_kernel(
    const float* __restrict__ x, float* __restrict__ out)
{
    int gid = blockIdx.x * 256 + threadIdx.x;   // = b*L + l
    int b = gid >> 12;
    int l = gid & (L - 1);

    float shift = 0.f;
#pragma unroll
    for (int zz = 0; zz < SPLIT; zz++) shift += g_part[(size_t)zz * BB * L + gid];

    float scale = (float)T / (float)L;
    float s = ((float)(l + 1) + shift) * scale;

    const float INV_AMP = (float)(1.0 / 1.772637204826652);
    float acc[8];
#pragma unroll
    for (int c = 0; c < 8; c++) acc[c] = 0.f;

    int lo = (int)ceilf(s - 6.0f);  if (lo < 1) lo = 1;
    int hi = (int)floorf(s + 6.0f); if (hi > T) hi = T;

    const float* xb = x + (size_t)b * T * C;
    for (int t = lo; t <= hi; t++) {
        float dd = (float)t - s;
        float wgt = expf(-dd * dd) * INV_AMP;
        const float4* xr = (const float4*)&xb[(t - 1) * C];
        float4 p0 = xr[0], p1 = xr[1];
        acc[0] += wgt * p0.x; acc[1] += wgt * p0.y;
        acc[2] += wgt * p0.z; acc[3] += wgt * p0.w;
        acc[4] += wgt * p1.x; acc[5] += wgt * p1.y;
        acc[6] += wgt * p1.z; acc[7] += wgt * p1.w;
    }
    float4* o = (float4*)&out[(size_t)gid * C];
    float4 r0 = {acc[0], acc[1], acc[2], acc[3]};
    float4 r1 = {acc[4], acc[5], acc[6], acc[7]};
    o[0] = r0; o[1] = r1;
}

// ---------------------------------------------------------------------------
extern "C" void kernel_launch(void* const* d_in, const int* in_sizes, int n_in,
                              void* d_out, int out_size)
{
    const float* x     = (const float*)d_in[0];
    const float* cw    = (const float*)d_in[1];
    const float* cb    = (const float*)d_in[2];
    const float* gamma = (const float*)d_in[3];
    const float* beta  = (const float*)d_in[4];
    const float* mean  = (const float*)d_in[5];
    const float* var   = (const float*)d_in[6];
    const float* dw    = (const float*)d_in[7];
    const float* db    = (const float*)d_in[8];
    float* out = (float*)d_out;

    const int GEMM_SMEM = F * 4 * 32 * 8 + F * 64 * 4;   // 64KB + 16KB
    cudaFuncSetAttribute(gemm_sig_kernel,
                         cudaFuncAttributeMaxDynamicSharedMemorySize, GEMM_SMEM);

    conv_bn_kernel<<<dim3(T / CONV_TT, BB), 256>>>(x, cw, cb, gamma, beta, mean, var);
    softmax_pe_kernel<<<BB * F, 256>>>();
    gemm_sig_kernel<<<dim3(L / GL, BB, SPLIT), 256, GEMM_SMEM>>>(dw, db);
    warp_kernel<<<(BB * L) / 256, 256>>>(x, out);
}

// round 6
// speedup vs baseline: 3.7699x; 1.9153x over previous
#include <cuda_runtime.h>
#include <cuda_bf16.h>
#include <math.h>
#include <stdint.h>

#define BB 16
#define T 4096
#define C 8
#define F 64
#define KW 11
#define PAD 5
#define L 4096
#define ZS 2            // z-split of t-range in MMA kernel
#define NTILE 32        // T/128 tiles (also L/128)

// ---- device scratch (no allocation allowed) ----
__device__ float g_h[BB * F * T];                                    // conv+bn out [B][F][T]
__device__ __nv_bfloat16 g_sbf[(size_t)BB * NTILE * 128 * 64];       // S tiles [b][tile][t][f] SW128
__device__ __nv_bfloat16 g_wbf[NTILE * 128 * 64];                    // W tiles [tile][l][f] SW128
__device__ float g_pe[F * T];                                        // positional encoding [F][T]
__device__ float g_pew[(size_t)T * L];                               // PE@W + bias, fp32 [T][L]
__device__ float g_part[ZS * BB * L];                                // partial shift sums

__device__ __forceinline__ uint32_t smem_u32(const void* p) {
    uint32_t a;
    asm("{ .reg .u64 t; cvta.to.shared.u64 t, %1; cvt.u32.u64 %0, t; }" : "=r"(a) : "l"(p));
    return a;
}
__host__ __device__ __forceinline__ uint32_t sw128(uint32_t off) {
    return off ^ ((off >> 3) & 0x70);
}

// ---------------------------------------------------------------------------
// K0a: positional encoding table g_pe[f][t]
// ---------------------------------------------------------------------------
__global__ void pe_kernel() {
    int idx = blockIdx.x * 256 + threadIdx.x;      // F*T
    int f = idx >> 12, t = idx & (T - 1);
    float ts = powf(1e-4f, (float)(2 * (f >> 1)) / 64.0f);
    float ang = (float)t * ts;
    g_pe[f * T + t] = (f & 1) ? cosf(ang) : sinf(ang);
}

// ---------------------------------------------------------------------------
// K0b: W -> bf16 swizzled tiles g_wbf[tile=l>>7][row=l&127][col=f]
// ---------------------------------------------------------------------------
__global__ void wprep_kernel(const float* __restrict__ dw) {
    int idx = blockIdx.x * 256 + threadIdx.x;      // F*L
    int f = idx >> 12, l = idx & (L - 1);
    int tile = l >> 7, r = l & 127;
    uint32_t off = sw128(r * 128 + f * 2);
    *(__nv_bfloat16*)((char*)g_wbf + (size_t)tile * 16384 + off) = __float2bfloat16(dw[idx]);
}

// ---------------------------------------------------------------------------
// K1: Conv1D(SAME) + BatchNorm -> g_h [B][F][T]
// ---------------------------------------------------------------------------
#define CONV_TT 64
__global__ __launch_bounds__(256) void conv_bn_kernel(
    const float* __restrict__ x, const float* __restrict__ cw,
    const float* __restrict__ cb, const float* __restrict__ gamma,
    const float* __restrict__ beta, const float* __restrict__ mean,
    const float* __restrict__ var)
{
    __shared__ float xs[(CONV_TT + KW - 1) * 9];
    __shared__ float ws[KW * C * F];
    __shared__ float sc[F], bi[F];

    int b = blockIdx.y;
    int t0 = blockIdx.x * CONV_TT;
    int tid = threadIdx.x;

    for (int idx = tid; idx < (CONV_TT + KW - 1) * 9; idx += 256) {
        int i = idx / 9, c = idx % 9;
        float v = 0.f;
        int tg = t0 + i - PAD;
        if (c < 8 && tg >= 0 && tg < T) v = x[(b * T + tg) * C + c];
        xs[idx] = v;
    }
    for (int idx = tid; idx < KW * C * F; idx += 256) ws[idx] = cw[idx];
    if (tid < F) {
        float s = gamma[tid] / sqrtf(var[tid] + 1e-3f);
        sc[tid] = s;
        bi[tid] = (cb[tid] - mean[tid]) * s + beta[tid];
    }
    __syncthreads();

    int tx = tid & 31;
    int ty = tid >> 5;
    float acc0[8], acc1[8];
#pragma unroll
    for (int j = 0; j < 8; j++) { acc0[j] = 0.f; acc1[j] = 0.f; }

#pragma unroll
    for (int k = 0; k < KW; k++) {
#pragma unroll
        for (int c = 0; c < C; c++) {
            float x0 = xs[(tx * 2 + k) * 9 + c];
            float x1 = xs[(tx * 2 + 1 + k) * 9 + c];
            const float* wrow = &ws[(k * C + c) * F + ty * 8];
#pragma unroll
            for (int j = 0; j < 8; j++) {
                float w = wrow[j];
                acc0[j] += x0 * w;
                acc1[j] += x1 * w;
            }
        }
    }
#pragma unroll
    for (int j = 0; j < 8; j++) {
        int f = ty * 8 + j;
        float s = sc[f], o = bi[f];
        float2 v;
        v.x = acc0[j] * s + o;
        v.y = acc1[j] * s + o;
        *(float2*)&g_h[(size_t)(b * F + f) * T + t0 + tx * 2] = v;
    }
}

// ---------------------------------------------------------------------------
// K2: softmax over T, in-place fp32 into g_h
// ---------------------------------------------------------------------------
__global__ __launch_bounds__(256) void softmax_kernel()
{
    int r = blockIdx.x;            // b*F + f
    float* row = g_h + (size_t)r * T;
    int tid = threadIdx.x;

    float v[16];
#pragma unroll
    for (int i = 0; i < 16; i++) v[i] = row[i * 256 + tid];

    float m = v[0];
#pragma unroll
    for (int i = 1; i < 16; i++) m = fmaxf(m, v[i]);

    __shared__ float sm[8], ss[8];
#pragma unroll
    for (int o = 16; o > 0; o >>= 1) m = fmaxf(m, __shfl_xor_sync(~0u, m, o));
    if ((tid & 31) == 0) sm[tid >> 5] = m;
    __syncthreads();
    m = sm[0];
#pragma unroll
    for (int w = 1; w < 8; w++) m = fmaxf(m, sm[w]);

    float e[16];
    float lsum = 0.f;
#pragma unroll
    for (int i = 0; i < 16; i++) { e[i] = expf(v[i] - m); lsum += e[i]; }
#pragma unroll
    for (int o = 16; o > 0; o >>= 1) lsum += __shfl_xor_sync(~0u, lsum, o);
    if ((tid & 31) == 0) ss[tid >> 5] = lsum;
    __syncthreads();
    float total = 0.f;
#pragma unroll
    for (int w = 0; w < 8; w++) total += ss[w];

    float inv = 1.f / total;
#pragma unroll
    for (int i = 0; i < 16; i++) row[i * 256 + tid] = e[i] * inv;
}

// ---------------------------------------------------------------------------
// K2b: transpose S -> bf16 swizzled tiles g_sbf[b][tile][t][f]
// ---------------------------------------------------------------------------
__global__ __launch_bounds__(256) void strans_kernel()
{
    __shared__ float st[64][130];
    int b = blockIdx.y;
    int tile = blockIdx.x;
    int tid = threadIdx.x;
    const float* src = g_h + (size_t)b * F * T + tile * 128;

#pragma unroll
    for (int it = 0; it < 8; it++) {
        int e = tid + it * 256;        // f = e/32, t4 = e%32
        int f = e >> 5, t4 = e & 31;
        float4 v = *(const float4*)(src + (size_t)f * T + t4 * 4);
        st[f][t4 * 4 + 0] = v.x; st[f][t4 * 4 + 1] = v.y;
        st[f][t4 * 4 + 2] = v.z; st[f][t4 * 4 + 3] = v.w;
    }
    __syncthreads();

    char* dst = (char*)g_sbf + ((size_t)b * NTILE + tile) * 16384;
#pragma unroll
    for (int it = 0; it < 4; it++) {
        int e = tid + it * 256;        // t = e>>3, fc = e&7
        int t = e >> 3, fc = e & 7;
        __nv_bfloat16 tmp[8];
#pragma unroll
        for (int j = 0; j < 8; j++) tmp[j] = __float2bfloat16(st[fc * 8 + j][t]);
        *(float4*)(dst + sw128(t * 128 + fc * 16)) = *(float4*)tmp;
    }
}

// ---------------------------------------------------------------------------
// K3: PEW = PE^T @ W + bias, fp32 FFMA2 GEMM -> g_pew [T][L]
// ---------------------------------------------------------------------------
#define FFMA2(acc, a, b) \
    asm("fma.rn.f32x2 %0, %1, %2, %0;" : "+l"(acc) : "l"(a), "l"(b))

__device__ __forceinline__ unsigned long long dup2(float a) {
    unsigned long long r;
    unsigned int u = __float_as_uint(a);
    asm("mov.b64 %0, {%1, %1};" : "=l"(r) : "r"(u));
    return r;
}

extern __shared__ __align__(16) unsigned char g_smem[];

__global__ __launch_bounds__(256) void pew_gemm_kernel(
    const float* __restrict__ dw, const float* __restrict__ db)
{
    unsigned long long* Ws = (unsigned long long*)g_smem;   // F*4*32 ull = 64KB
    float* As = (float*)(g_smem + F * 4 * 32 * 8);          // F*64 floats = 16KB

    int l0 = blockIdx.x * 256;
    int tb0 = blockIdx.y * 64;
    int tid = threadIdx.x;
    int lane = tid & 31;
    int wy = tid >> 5;

#pragma unroll
    for (int it = 0; it < 16; it++) {
        int e = tid + it * 256;
        int f = e >> 6, j4 = e & 63;
        float4 v = *(const float4*)(dw + (size_t)f * L + l0 + j4 * 4);
        int lw = j4 >> 1;
        int pb = (j4 & 1) * 2;
        unsigned long long u0 = (unsigned long long)__float_as_uint(v.x) |
                                ((unsigned long long)__float_as_uint(v.y) << 32);
        unsigned long long u1 = (unsigned long long)__float_as_uint(v.z) |
                                ((unsigned long long)__float_as_uint(v.w) << 32);
        Ws[f * 128 + pb * 32 + lw] = u0;
        Ws[f * 128 + (pb + 1) * 32 + lw] = u1;
    }

    float4* As4 = (float4*)As;
    const float4* a4 = (const float4*)g_pe;
#pragma unroll
    for (int it = 0; it < 4; it++) {
        int e = tid + it * 256;
        int f = e >> 4, j4 = e & 15;
        As4[f * 16 + j4] = a4[f * (T / 4) + (tb0 >> 2) + j4];
    }
    __syncthreads();

    float breg[8];
#pragma unroll
    for (int j = 0; j < 8; j++) breg[j] = db[l0 + lane * 8 + j];

    unsigned long long acc[8][4];
#pragma unroll
    for (int i = 0; i < 8; i++)
#pragma unroll
        for (int p = 0; p < 4; p++) acc[i][p] = 0ull;

#pragma unroll 4
    for (int f = 0; f < F; f++) {
        float4 a03 = As4[f * 16 + wy * 2];
        float4 a47 = As4[f * 16 + wy * 2 + 1];
        unsigned long long ad[8];
        ad[0] = dup2(a03.x); ad[1] = dup2(a03.y);
        ad[2] = dup2(a03.z); ad[3] = dup2(a03.w);
        ad[4] = dup2(a47.x); ad[5] = dup2(a47.y);
        ad[6] = dup2(a47.z); ad[7] = dup2(a47.w);
        unsigned long long w[4];
#pragma unroll
        for (int p = 0; p < 4; p++) w[p] = Ws[f * 128 + p * 32 + lane];
#pragma unroll
        for (int i = 0; i < 8; i++)
#pragma unroll
            for (int p = 0; p < 4; p++) FFMA2(acc[i][p], ad[i], w[p]);
    }

#pragma unroll
    for (int i = 0; i < 8; i++) {
        int trow = tb0 + wy * 8 + i;
        float* orow = g_pew + (size_t)trow * L + l0 + lane * 8;
#pragma unroll
        for (int p = 0; p < 4; p++) {
            float2 v = *(float2*)&acc[i][p];
            float2 o;
            o.x = v.x + breg[2 * p];
            o.y = v.y + breg[2 * p + 1];
            *(float2*)(orow + 2 * p) = o;
        }
    }
}

// ---------------------------------------------------------------------------
// K4: HMMA bf16 (S @ W) + PEW + sigmoid + t-sum -> g_part
// CTA: 128 l x 16 t-tiles of 128; 256 threads = 8 warps (2 tq x 4 lq)
// mma.sync.m16n8k16 row.col, ldmatrix fragments, double-buffered S tiles
// ---------------------------------------------------------------------------
__device__ __forceinline__ void ldsm4(uint32_t* r, uint32_t addr) {
    asm volatile("ldmatrix.sync.aligned.m8n8.x4.shared.b16 {%0,%1,%2,%3}, [%4];"
                 : "=r"(r[0]), "=r"(r[1]), "=r"(r[2]), "=r"(r[3]) : "r"(addr));
}
__device__ __forceinline__ void mma16816(float* c, const uint32_t* a, const uint32_t* b) {
    asm volatile(
        "mma.sync.aligned.m16n8k16.row.col.f32.bf16.bf16.f32 "
        "{%0,%1,%2,%3}, {%4,%5,%6,%7}, {%8,%9}, {%0,%1,%2,%3};"
        : "+f"(c[0]), "+f"(c[1]), "+f"(c[2]), "+f"(c[3])
        : "r"(a[0]), "r"(a[1]), "r"(a[2]), "r"(a[3]), "r"(b[0]), "r"(b[1]));
}

__global__ __launch_bounds__(256) void hmma_sig_kernel()
{
    unsigned char* dsm = g_smem;      // [0,16K)=W  [16K,32K)=S0  [32K,48K)=S1
    int b = blockIdx.y, zz = blockIdx.z;
    int l0 = blockIdx.x * 128;
    int tid = threadIdx.x, lane = tid & 31, w = tid >> 5;
    int tq = w >> 2, lq = w & 3;

    // W tile copy (pre-swizzled 16KB)
    {
        const float4* ws = (const float4*)((const char*)g_wbf + (size_t)blockIdx.x * 16384);
        float4* wd = (float4*)dsm;
#pragma unroll
        for (int i = 0; i < 4; i++) wd[tid + i * 256] = ws[tid + i * 256];
    }
    const char* sbase_g = (const char*)g_sbf + ((size_t)b * NTILE + zz * 16) * 16384;
    // prologue: S tile 0
    {
        const float4* s4 = (const float4*)sbase_g;
        float4* d4 = (float4*)(dsm + 16384);
#pragma unroll
        for (int i = 0; i < 4; i++) d4[tid + i * 256] = s4[tid + i * 256];
    }
    __syncthreads();

    uint32_t wbase = smem_u32(dsm);
    uint32_t sbufa0 = wbase + 16384, sbufa1 = wbase + 32768;

    // B fragments: constant over all tiles (W tile never changes)
    uint32_t Bf[4][4][2];     // [nfrag][kstep][2]
    {
        int grp = lane >> 3;
        int nrow = lq * 32 + ((grp & 2) << 2) + (lane & 7);
        int kh = grp & 1;
#pragma unroll
        for (int p = 0; p < 2; p++) {
#pragma unroll
            for (int k = 0; k < 4; k++) {
                uint32_t off = (uint32_t)(nrow + p * 16) * 128 + k * 32 + kh * 16;
                uint32_t r[4];
                ldsm4(r, wbase + sw128(off));
                Bf[2 * p][k][0] = r[0];     Bf[2 * p][k][1] = r[1];
                Bf[2 * p + 1][k][0] = r[2]; Bf[2 * p + 1][k][1] = r[3];
            }
        }
    }

    float dacc[8];
#pragma unroll
    for (int j = 0; j < 8; j++) dacc[j] = 0.f;

    int arow = (lane & 15);
    int akh = lane >> 4;

    for (int i = 0; i < 16; i++) {
        int cur = i & 1;
        uint32_t sA = cur ? sbufa1 : sbufa0;

        // prefetch next S tile into registers
        float4 creg[4];
        if (i + 1 < 16) {
            const float4* s4 = (const float4*)(sbase_g + (size_t)(i + 1) * 16384);
#pragma unroll
            for (int j = 0; j < 4; j++) creg[j] = s4[tid + j * 256];
        }

#pragma unroll
        for (int tf = 0; tf < 4; tf++) {
            int row = tq * 64 + tf * 16 + arow;
            uint32_t Af[4][4];
#pragma unroll
            for (int k = 0; k < 4; k++) {
                uint32_t off = (uint32_t)row * 128 + k * 32 + akh * 16;
                ldsm4(Af[k], sA + sw128(off));
            }
            float c[4][4];
#pragma unroll
            for (int nf = 0; nf < 4; nf++)
#pragma unroll
                for (int q = 0; q < 4; q++) c[nf][q] = 0.f;
#pragma unroll
            for (int k = 0; k < 4; k++)
#pragma unroll
                for (int nf = 0; nf < 4; nf++) mma16816(c[nf], Af[k], Bf[nf][k]);

            // epilogue: z = c + pew; d = (1-e^-z)/(1+e^-z); accumulate per l
            int trow = (zz * 16 + i) * 128 + tq * 64 + tf * 16 + (lane >> 2);
            const float* pr = g_pew + (size_t)trow * L + l0 + lq * 32 + (lane & 3) * 2;
#pragma unroll
            for (int nf = 0; nf < 4; nf++) {
                float2 p0 = *(const float2*)(pr + nf * 8);
                float2 p1 = *(const float2*)(pr + nf * 8 + 8 * L);
                float z, e;
                z = c[nf][0] + p0.x; e = __expf(-z);
                dacc[nf * 2 + 0] += __fdividef(1.f - e, 1.f + e);
                z = c[nf][1] + p0.y; e = __expf(-z);
                dacc[nf * 2 + 1] += __fdividef(1.f - e, 1.f + e);
                z = c[nf][2] + p1.x; e = __expf(-z);
                dacc[nf * 2 + 0] += __fdividef(1.f - e, 1.f + e);
                z = c[nf][3] + p1.y; e = __expf(-z);
                dacc[nf * 2 + 1] += __fdividef(1.f - e, 1.f + e);
            }
        }

        if (i + 1 < 16) {
            float4* d4 = (float4*)(dsm + 16384 + (cur ^ 1) * 16384);
#pragma unroll
            for (int j = 0; j < 4; j++) d4[tid + j * 256] = creg[j];
        }
        __syncthreads();
    }

    // reduce over lanes sharing the same column set (lane%4 fixed)
#pragma unroll
    for (int o = 4; o < 32; o <<= 1)
#pragma unroll
        for (int j = 0; j < 8; j++) dacc[j] += __shfl_xor_sync(~0u, dacc[j], o);

    float* red = (float*)dsm;      // reuse W region (no longer needed)
    if (lane < 4) {
#pragma unroll
        for (int nf = 0; nf < 4; nf++) {
            red[tq * 128 + lq * 32 + nf * 8 + lane * 2 + 0] = dacc[nf * 2 + 0];
            red[tq * 128 + lq * 32 + nf * 8 + lane * 2 + 1] = dacc[nf * 2 + 1];
        }
    }
    __syncthreads();
    if (tid < 128)
        g_part[((size_t)zz * BB + b) * L + l0 + tid] = red[tid] + red[128 + tid];
}

// ---------------------------------------------------------------------------
// K5: Gaussian RBF warp — combines split partials, truncated window |d| <= 6
// ---------------------------------------------------------------------------
__global__ __launch_bounds__(256) void warp_kernel(
    const float* __restrict__ x, float* __restrict__ out)
{
    int gid = blockIdx.x * 256 + threadIdx.x;   // = b*L + l
    int b = gid >> 12;
    int l = gid & (L - 1);

    float shift = 0.f;
#pragma unroll
    for (int zz = 0; zz < ZS; zz++) shift += g_part[(size_t)zz * BB * L + gid];

    float scale = (float)T / (float)L;
    float s = ((float)(l + 1) + shift) * scale;

    const float INV_AMP = (float)(1.0 / 1.772637204826652);
    float acc[8];
#pragma unroll
    for (int c = 0; c < 8; c++) acc[c] = 0.f;

    int lo = (int)ceilf(s - 6.0f);  if (lo < 1) lo = 1;
    int hi = (int)floorf(s + 6.0f); if (hi > T) hi = T;

    const float* xb = x + (size_t)b * T * C;
    for (int t = lo; t <= hi; t++) {
        float dd = (float)t - s;
        float wgt = expf(-dd * dd) * INV_AMP;
        const float4* xr = (const float4*)&xb[(t - 1) * C];
        float4 p0 = xr[0], p1 = xr[1];
        acc[0] += wgt * p0.x; acc[1] += wgt * p0.y;
        acc[2] += wgt * p0.z; acc[3] += wgt * p0.w;
        acc[4] += wgt * p1.x; acc[5] += wgt * p1.y;
        acc[6] += wgt * p1.z; acc[7] += wgt * p1.w;
    }
    float4* o = (float4*)&out[(size_t)gid * C];
    float4 r0 = {acc[0], acc[1], acc[2], acc[3]};
    float4 r1 = {acc[4], acc[5], acc[6], acc[7]};
    o[0] = r0; o[1] = r1;
}

// ---------------------------------------------------------------------------
extern "C" void kernel_launch(void* const* d_in, const int* in_sizes, int n_in,
                              void* d_out, int out_size)
{
    const float* x     = (const float*)d_in[0];
    const float* cw    = (const float*)d_in[1];
    const float* cb    = (const float*)d_in[2];
    const float* gamma = (const float*)d_in[3];
    const float* beta  = (const float*)d_in[4];
    const float* mean  = (const float*)d_in[5];
    const float* var   = (const float*)d_in[6];
    const float* dw    = (const float*)d_in[7];
    const float* db    = (const float*)d_in[8];
    float* out = (float*)d_out;

    const int PEW_SMEM = F * 4 * 32 * 8 + F * 64 * 4;   // 80KB
    cudaFuncSetAttribute(pew_gemm_kernel,
                         cudaFuncAttributeMaxDynamicSharedMemorySize, PEW_SMEM);
    const int HMMA_SMEM = 3 * 16384;                    // 48KB
    cudaFuncSetAttribute(hmma_sig_kernel,
                         cudaFuncAttributeMaxDynamicSharedMemorySize, HMMA_SMEM);

    pe_kernel<<<(F * T) / 256, 256>>>();
    wprep_kernel<<<(F * L) / 256, 256>>>(dw);
    conv_bn_kernel<<<dim3(T / CONV_TT, BB), 256>>>(x, cw, cb, gamma, beta, mean, var);
    softmax_kernel<<<BB * F, 256>>>();
    strans_kernel<<<dim3(NTILE, BB), 256>>>();
    pew_gemm_kernel<<<dim3(L / 256, T / 64), 256, PEW_SMEM>>>(dw, db);
    hmma_sig_kernel<<<dim3(L / 128, BB, ZS), 256, HMMA_SMEM>>>();
    warp_kernel<<<(BB * L) / 256, 256>>>(x, out);
}

// round 7
// speedup vs baseline: 3.7724x; 1.0007x over previous
#include <cuda_runtime.h>
#include <cuda_fp16.h>
#include <math.h>
#include <stdint.h>

#define BB 16
#define T 4096
#define C 8
#define F 64
#define KW 11
#define PAD 5
#define L 4096
#define ZS 2            // z-split of t-range in MMA kernel
#define NTILE 32        // T/128 tiles (also L/128)

// ---- device scratch (no allocation allowed) ----
__device__ float g_h[BB * F * T];                              // conv+bn out [B][F][T]
__device__ __half g_sbf[(size_t)BB * NTILE * 128 * 64];        // S tiles [b][tile][t][f] SW128
__device__ __half g_wbf[NTILE * 128 * 64];                     // W tiles [tile][l][f] SW128
__device__ float g_pe[F * T];                                  // positional encoding [F][T]
__device__ float g_pew[(size_t)T * L];                         // PE@W + bias, fp32 [T][L]
__device__ float g_part[ZS * BB * L];                          // partial shift sums

__device__ __forceinline__ uint32_t smem_u32(const void* p) {
    uint32_t a;
    asm("{ .reg .u64 t; cvta.to.shared.u64 t, %1; cvt.u32.u64 %0, t; }" : "=r"(a) : "l"(p));
    return a;
}
__host__ __device__ __forceinline__ uint32_t sw128(uint32_t off) {
    return off ^ ((off >> 3) & 0x70);
}

// ---------------------------------------------------------------------------
// K0a: positional encoding table g_pe[f][t]
// ---------------------------------------------------------------------------
__global__ void pe_kernel() {
    int idx = blockIdx.x * 256 + threadIdx.x;      // F*T
    int f = idx >> 12, t = idx & (T - 1);
    float ts = powf(1e-4f, (float)(2 * (f >> 1)) / 64.0f);
    float ang = (float)t * ts;
    g_pe[f * T + t] = (f & 1) ? cosf(ang) : sinf(ang);
}

// ---------------------------------------------------------------------------
// K0b: W -> fp16 swizzled tiles g_wbf[tile=l>>7][row=l&127][col=f]
// ---------------------------------------------------------------------------
__global__ void wprep_kernel(const float* __restrict__ dw) {
    int idx = blockIdx.x * 256 + threadIdx.x;      // F*L
    int f = idx >> 12, l = idx & (L - 1);
    int tile = l >> 7, r = l & 127;
    uint32_t off = sw128(r * 128 + f * 2);
    *(__half*)((char*)g_wbf + (size_t)tile * 16384 + off) = __float2half(dw[idx]);
}

// ---------------------------------------------------------------------------
// K1: Conv1D(SAME) + BatchNorm -> g_h [B][F][T]
// ---------------------------------------------------------------------------
#define CONV_TT 64
__global__ __launch_bounds__(256) void conv_bn_kernel(
    const float* __restrict__ x, const float* __restrict__ cw,
    const float* __restrict__ cb, const float* __restrict__ gamma,
    const float* __restrict__ beta, const float* __restrict__ mean,
    const float* __restrict__ var)
{
    __shared__ float xs[(CONV_TT + KW - 1) * 9];
    __shared__ float ws[KW * C * F];
    __shared__ float sc[F], bi[F];

    int b = blockIdx.y;
    int t0 = blockIdx.x * CONV_TT;
    int tid = threadIdx.x;

    for (int idx = tid; idx < (CONV_TT + KW - 1) * 9; idx += 256) {
        int i = idx / 9, c = idx % 9;
        float v = 0.f;
        int tg = t0 + i - PAD;
        if (c < 8 && tg >= 0 && tg < T) v = x[(b * T + tg) * C + c];
        xs[idx] = v;
    }
    for (int idx = tid; idx < KW * C * F; idx += 256) ws[idx] = cw[idx];
    if (tid < F) {
        float s = gamma[tid] / sqrtf(var[tid] + 1e-3f);
        sc[tid] = s;
        bi[tid] = (cb[tid] - mean[tid]) * s + beta[tid];
    }
    __syncthreads();

    int tx = tid & 31;
    int ty = tid >> 5;
    float acc0[8], acc1[8];
#pragma unroll
    for (int j = 0; j < 8; j++) { acc0[j] = 0.f; acc1[j] = 0.f; }

#pragma unroll
    for (int k = 0; k < KW; k++) {
#pragma unroll
        for (int c = 0; c < C; c++) {
            float x0 = xs[(tx * 2 + k) * 9 + c];
            float x1 = xs[(tx * 2 + 1 + k) * 9 + c];
            const float* wrow = &ws[(k * C + c) * F + ty * 8];
#pragma unroll
            for (int j = 0; j < 8; j++) {
                float w = wrow[j];
                acc0[j] += x0 * w;
                acc1[j] += x1 * w;
            }
        }
    }
#pragma unroll
    for (int j = 0; j < 8; j++) {
        int f = ty * 8 + j;
        float s = sc[f], o = bi[f];
        float2 v;
        v.x = acc0[j] * s + o;
        v.y = acc1[j] * s + o;
        *(float2*)&g_h[(size_t)(b * F + f) * T + t0 + tx * 2] = v;
    }
}

// ---------------------------------------------------------------------------
// K2: softmax over T, in-place fp32 into g_h
// ---------------------------------------------------------------------------
__global__ __launch_bounds__(256) void softmax_kernel()
{
    int r = blockIdx.x;            // b*F + f
    float* row = g_h + (size_t)r * T;
    int tid = threadIdx.x;

    float v[16];
#pragma unroll
    for (int i = 0; i < 16; i++) v[i] = row[i * 256 + tid];

    float m = v[0];
#pragma unroll
    for (int i = 1; i < 16; i++) m = fmaxf(m, v[i]);

    __shared__ float sm[8], ss[8];
#pragma unroll
    for (int o = 16; o > 0; o >>= 1) m = fmaxf(m, __shfl_xor_sync(~0u, m, o));
    if ((tid & 31) == 0) sm[tid >> 5] = m;
    __syncthreads();
    m = sm[0];
#pragma unroll
    for (int w = 1; w < 8; w++) m = fmaxf(m, sm[w]);

    float e[16];
    float lsum = 0.f;
#pragma unroll
    for (int i = 0; i < 16; i++) { e[i] = expf(v[i] - m); lsum += e[i]; }
#pragma unroll
    for (int o = 16; o > 0; o >>= 1) lsum += __shfl_xor_sync(~0u, lsum, o);
    if ((tid & 31) == 0) ss[tid >> 5] = lsum;
    __syncthreads();
    float total = 0.f;
#pragma unroll
    for (int w = 0; w < 8; w++) total += ss[w];

    float inv = 1.f / total;
#pragma unroll
    for (int i = 0; i < 16; i++) row[i * 256 + tid] = e[i] * inv;
}

// ---------------------------------------------------------------------------
// K2b: transpose S -> fp16 swizzled tiles g_sbf[b][tile][t][f]
// ---------------------------------------------------------------------------
__global__ __launch_bounds__(256) void strans_kernel()
{
    __shared__ float st[64][130];
    int b = blockIdx.y;
    int tile = blockIdx.x;
    int tid = threadIdx.x;
    const float* src = g_h + (size_t)b * F * T + tile * 128;

#pragma unroll
    for (int it = 0; it < 8; it++) {
        int e = tid + it * 256;        // f = e/32, t4 = e%32
        int f = e >> 5, t4 = e & 31;
        float4 v = *(const float4*)(src + (size_t)f * T + t4 * 4);
        st[f][t4 * 4 + 0] = v.x; st[f][t4 * 4 + 1] = v.y;
        st[f][t4 * 4 + 2] = v.z; st[f][t4 * 4 + 3] = v.w;
    }
    __syncthreads();

    char* dst = (char*)g_sbf + ((size_t)b * NTILE + tile) * 16384;
#pragma unroll
    for (int it = 0; it < 4; it++) {
        int e = tid + it * 256;        // t = e>>3, fc = e&7
        int t = e >> 3, fc = e & 7;
        __half tmp[8];
#pragma unroll
        for (int j = 0; j < 8; j++) tmp[j] = __float2half(st[fc * 8 + j][t]);
        *(float4*)(dst + sw128(t * 128 + fc * 16)) = *(float4*)tmp;
    }
}

// ---------------------------------------------------------------------------
// K3: PEW = PE^T @ W + bias, fp32 FFMA2 GEMM -> g_pew [T][L]
// ---------------------------------------------------------------------------
#define FFMA2(acc, a, b) \
    asm("fma.rn.f32x2 %0, %1, %2, %0;" : "+l"(acc) : "l"(a), "l"(b))

__device__ __forceinline__ unsigned long long dup2(float a) {
    unsigned long long r;
    unsigned int u = __float_as_uint(a);
    asm("mov.b64 %0, {%1, %1};" : "=l"(r) : "r"(u));
    return r;
}

extern __shared__ __align__(16) unsigned char g_smem[];

__global__ __launch_bounds__(256) void pew_gemm_kernel(
    const float* __restrict__ dw, const float* __restrict__ db)
{
    unsigned long long* Ws = (unsigned long long*)g_smem;   // F*4*32 ull = 64KB
    float* As = (float*)(g_smem + F * 4 * 32 * 8);          // F*64 floats = 16KB

    int l0 = blockIdx.x * 256;
    int tb0 = blockIdx.y * 64;
    int tid = threadIdx.x;
    int lane = tid & 31;
    int wy = tid >> 5;

#pragma unroll
    for (int it = 0; it < 16; it++) {
        int e = tid + it * 256;
        int f = e >> 6, j4 = e & 63;
        float4 v = *(const float4*)(dw + (size_t)f * L + l0 + j4 * 4);
        int lw = j4 >> 1;
        int pb = (j4 & 1) * 2;
        unsigned long long u0 = (unsigned long long)__float_as_uint(v.x) |
                                ((unsigned long long)__float_as_uint(v.y) << 32);
        unsigned long long u1 = (unsigned long long)__float_as_uint(v.z) |
                                ((unsigned long long)__float_as_uint(v.w) << 32);
        Ws[f * 128 + pb * 32 + lw] = u0;
        Ws[f * 128 + (pb + 1) * 32 + lw] = u1;
    }

    float4* As4 = (float4*)As;
    const float4* a4 = (const float4*)g_pe;
#pragma unroll
    for (int it = 0; it < 4; it++) {
        int e = tid + it * 256;
        int f = e >> 4, j4 = e & 15;
        As4[f * 16 + j4] = a4[f * (T / 4) + (tb0 >> 2) + j4];
    }
    __syncthreads();

    float breg[8];
#pragma unroll
    for (int j = 0; j < 8; j++) breg[j] = db[l0 + lane * 8 + j];

    unsigned long long acc[8][4];
#pragma unroll
    for (int i = 0; i < 8; i++)
#pragma unroll
        for (int p = 0; p < 4; p++) acc[i][p] = 0ull;

#pragma unroll 4
    for (int f = 0; f < F; f++) {
        float4 a03 = As4[f * 16 + wy * 2];
        float4 a47 = As4[f * 16 + wy * 2 + 1];
        unsigned long long ad[8];
        ad[0] = dup2(a03.x); ad[1] = dup2(a03.y);
        ad[2] = dup2(a03.z); ad[3] = dup2(a03.w);
        ad[4] = dup2(a47.x); ad[5] = dup2(a47.y);
        ad[6] = dup2(a47.z); ad[7] = dup2(a47.w);
        unsigned long long w[4];
#pragma unroll
        for (int p = 0; p < 4; p++) w[p] = Ws[f * 128 + p * 32 + lane];
#pragma unroll
        for (int i = 0; i < 8; i++)
#pragma unroll
            for (int p = 0; p < 4; p++) FFMA2(acc[i][p], ad[i], w[p]);
    }

#pragma unroll
    for (int i = 0; i < 8; i++) {
        int trow = tb0 + wy * 8 + i;
        float* orow = g_pew + (size_t)trow * L + l0 + lane * 8;
#pragma unroll
        for (int p = 0; p < 4; p++) {
            float2 v = *(float2*)&acc[i][p];
            float2 o;
            o.x = v.x + breg[2 * p];
            o.y = v.y + breg[2 * p + 1];
            *(float2*)(orow + 2 * p) = o;
        }
    }
}

// ---------------------------------------------------------------------------
// K4: HMMA fp16 (S @ W) + PEW + sigmoid + t-sum -> g_part
// CTA: 128 l x 16 t-tiles of 128; 256 threads = 8 warps (2 tq x 4 lq)
// grid: (BB, L/128, ZS) — b fastest so concurrent CTAs share PEW/W in L2
// ---------------------------------------------------------------------------
__device__ __forceinline__ void ldsm4(uint32_t* r, uint32_t addr) {
    asm volatile("ldmatrix.sync.aligned.m8n8.x4.shared.b16 {%0,%1,%2,%3}, [%4];"
                 : "=r"(r[0]), "=r"(r[1]), "=r"(r[2]), "=r"(r[3]) : "r"(addr));
}
__device__ __forceinline__ void mma16816(float* c, const uint32_t* a, const uint32_t* b) {
    asm volatile(
        "mma.sync.aligned.m16n8k16.row.col.f32.f16.f16.f32 "
        "{%0,%1,%2,%3}, {%4,%5,%6,%7}, {%8,%9}, {%0,%1,%2,%3};"
        : "+f"(c[0]), "+f"(c[1]), "+f"(c[2]), "+f"(c[3])
        : "r"(a[0]), "r"(a[1]), "r"(a[2]), "r"(a[3]), "r"(b[0]), "r"(b[1]));
}

__global__ __launch_bounds__(256) void hmma_sig_kernel()
{
    unsigned char* dsm = g_smem;      // [0,16K)=W  [16K,32K)=S0  [32K,48K)=S1
    int b = blockIdx.x, zz = blockIdx.z;
    int ltile = blockIdx.y;
    int l0 = ltile * 128;
    int tid = threadIdx.x, lane = tid & 31, w = tid >> 5;
    int tq = w >> 2, lq = w & 3;

    // W tile copy (pre-swizzled 16KB)
    {
        const float4* ws = (const float4*)((const char*)g_wbf + (size_t)ltile * 16384);
        float4* wd = (float4*)dsm;
#pragma unroll
        for (int i = 0; i < 4; i++) wd[tid + i * 256] = ws[tid + i * 256];
    }
    const char* sbase_g = (const char*)g_sbf + ((size_t)b * NTILE + zz * 16) * 16384;
    // prologue: S tile 0
    {
        const float4* s4 = (const float4*)sbase_g;
        float4* d4 = (float4*)(dsm + 16384);
#pragma unroll
        for (int i = 0; i < 4; i++) d4[tid + i * 256] = s4[tid + i * 256];
    }
    __syncthreads();

    uint32_t wbase = smem_u32(dsm);
    uint32_t sbufa0 = wbase + 16384, sbufa1 = wbase + 32768;

    // B fragments: constant over all tiles (W tile never changes)
    uint32_t Bf[4][4][2];     // [nfrag][kstep][2]
    {
        int grp = lane >> 3;
        int nrow = lq * 32 + ((grp & 2) << 2) + (lane & 7);
        int kh = grp & 1;
#pragma unroll
        for (int p = 0; p < 2; p++) {
#pragma unroll
            for (int k = 0; k < 4; k++) {
                uint32_t off = (uint32_t)(nrow + p * 16) * 128 + k * 32 + kh * 16;
                uint32_t r[4];
                ldsm4(r, wbase + sw128(off));
                Bf[2 * p][k][0] = r[0];     Bf[2 * p][k][1] = r[1];
                Bf[2 * p + 1][k][0] = r[2]; Bf[2 * p + 1][k][1] = r[3];
            }
        }
    }

    float dacc[8];
#pragma unroll
    for (int j = 0; j < 8; j++) dacc[j] = 0.f;

    int arow = (lane & 15);
    int akh = lane >> 4;

    for (int i = 0; i < 16; i++) {
        int cur = i & 1;
        uint32_t sA = cur ? sbufa1 : sbufa0;

        // prefetch next S tile into registers
        float4 creg[4];
        if (i + 1 < 16) {
            const float4* s4 = (const float4*)(sbase_g + (size_t)(i + 1) * 16384);
#pragma unroll
            for (int j = 0; j < 4; j++) creg[j] = s4[tid + j * 256];
        }

#pragma unroll
        for (int tf = 0; tf < 4; tf++) {
            int row = tq * 64 + tf * 16 + arow;
            uint32_t Af[4][4];
#pragma unroll
            for (int k = 0; k < 4; k++) {
                uint32_t off = (uint32_t)row * 128 + k * 32 + akh * 16;
                ldsm4(Af[k], sA + sw128(off));
            }
            float c[4][4];
#pragma unroll
            for (int nf = 0; nf < 4; nf++)
#pragma unroll
                for (int q = 0; q < 4; q++) c[nf][q] = 0.f;
#pragma unroll
            for (int k = 0; k < 4; k++)
#pragma unroll
                for (int nf = 0; nf < 4; nf++) mma16816(c[nf], Af[k], Bf[nf][k]);

            // epilogue: z = c + pew; accumulate 2*sigmoid(z); -1 corrected at end
            int trow = (zz * 16 + i) * 128 + tq * 64 + tf * 16 + (lane >> 2);
            const float* pr = g_pew + (size_t)trow * L + l0 + lq * 32 + (lane & 3) * 2;
#pragma unroll
            for (int nf = 0; nf < 4; nf++) {
                float2 p0 = *(const float2*)(pr + nf * 8);
                float2 p1 = *(const float2*)(pr + nf * 8 + 8 * L);
                float z, e;
                z = c[nf][0] + p0.x; e = __expf(-z);
                dacc[nf * 2 + 0] += __fdividef(2.f, 1.f + e);
                z = c[nf][1] + p0.y; e = __expf(-z);
                dacc[nf * 2 + 1] += __fdividef(2.f, 1.f + e);
                z = c[nf][2] + p1.x; e = __expf(-z);
                dacc[nf * 2 + 0] += __fdividef(2.f, 1.f + e);
                z = c[nf][3] + p1.y; e = __expf(-z);
                dacc[nf * 2 + 1] += __fdividef(2.f, 1.f + e);
            }
        }

        if (i + 1 < 16) {
            float4* d4 = (float4*)(dsm + 16384 + (cur ^ 1) * 16384);
#pragma unroll
            for (int j = 0; j < 4; j++) d4[tid + j * 256] = creg[j];
        }
        __syncthreads();
    }

    // each dacc slot accumulated exactly 16*4*2 = 128 elements of 2*sigmoid
#pragma unroll
    for (int j = 0; j < 8; j++) dacc[j] -= 128.f;

    // reduce over lanes sharing the same column set (lane%4 fixed)
#pragma unroll
    for (int o = 4; o < 32; o <<= 1)
#pragma unroll
        for (int j = 0; j < 8; j++) dacc[j] += __shfl_xor_sync(~0u, dacc[j], o);

    float* red = (float*)dsm;      // reuse W region (no longer needed)
    if (lane < 4) {
#pragma unroll
        for (int nf = 0; nf < 4; nf++) {
            red[tq * 128 + lq * 32 + nf * 8 + lane * 2 + 0] = dacc[nf * 2 + 0];
            red[tq * 128 + lq * 32 + nf * 8 + lane * 2 + 1] = dacc[nf * 2 + 1];
        }
    }
    __syncthreads();
    if (tid < 128)
        g_part[((size_t)zz * BB + b) * L + l0 + tid] = red[tid] + red[128 + tid];
}

// ---------------------------------------------------------------------------
// K5: Gaussian RBF warp — combines split partials, truncated window |d| <= 6
// ---------------------------------------------------------------------------
__global__ __launch_bounds__(256) void warp_kernel(
    const float* __restrict__ x, float* __restrict__ out)
{
    int gid = blockIdx.x * 256 + threadIdx.x;   // = b*L + l
    int b = gid >> 12;
    int l = gid & (L - 1);

    float shift = 0.f;
#pragma unroll
    for (int zz = 0; zz < ZS; zz++) shift += g_part[(size_t)zz * BB * L + gid];

    float scale = (float)T / (float)L;
    float s = ((float)(l + 1) + shift) * scale;

    const float INV_AMP = (float)(1.0 / 1.772637204826652);
    float acc[8];
#pragma unroll
    for (int c = 0; c < 8; c++) acc[c] = 0.f;

    int lo = (int)ceilf(s - 6.0f);  if (lo < 1) lo = 1;
    int hi = (int)floorf(s + 6.0f); if (hi > T) hi = T;

    const float* xb = x + (size_t)b * T * C;
    for (int t = lo; t <= hi; t++) {
        float dd = (float)t - s;
        float wgt = expf(-dd * dd) * INV_AMP;
        const float4* xr = (const float4*)&xb[(t - 1) * C];
        float4 p0 = xr[0], p1 = xr[1];
        acc[0] += wgt * p0.x; acc[1] += wgt * p0.y;
        acc[2] += wgt * p0.z; acc[3] += wgt * p0.w;
        acc[4] += wgt * p1.x; acc[5] += wgt * p1.y;
        acc[6] += wgt * p1.z; acc[7] += wgt * p1.w;
    }
    float4* o = (float4*)&out[(size_t)gid * C];
    float4 r0 = {acc[0], acc[1], acc[2], acc[3]};
    float4 r1 = {acc[4], acc[5], acc[6], acc[7]};
    o[0] = r0; o[1] = r1;
}

// ---------------------------------------------------------------------------
extern "C" void kernel_launch(void* const* d_in, const int* in_sizes, int n_in,
                              void* d_out, int out_size)
{
    const float* x     = (const float*)d_in[0];
    const float* cw    = (const float*)d_in[1];
    const float* cb    = (const float*)d_in[2];
    const float* gamma = (const float*)d_in[3];
    const float* beta  = (const float*)d_in[4];
    const float* mean  = (const float*)d_in[5];
    const float* var   = (const float*)d_in[6];
    const float* dw    = (const float*)d_in[7];
    const float* db    = (const float*)d_in[8];
    float* out = (float*)d_out;

    const int PEW_SMEM = F * 4 * 32 * 8 + F * 64 * 4;   // 80KB
    cudaFuncSetAttribute(pew_gemm_kernel,
                         cudaFuncAttributeMaxDynamicSharedMemorySize, PEW_SMEM);
    const int HMMA_SMEM = 3 * 16384;                    // 48KB
    cudaFuncSetAttribute(hmma_sig_kernel,
                         cudaFuncAttributeMaxDynamicSharedMemorySize, HMMA_SMEM);

    pe_kernel<<<(F * T) / 256, 256>>>();
    wprep_kernel<<<(F * L) / 256, 256>>>(dw);
    conv_bn_kernel<<<dim3(T / CONV_TT, BB), 256>>>(x, cw, cb, gamma, beta, mean, var);
    softmax_kernel<<<BB * F, 256>>>();
    strans_kernel<<<dim3(NTILE, BB), 256>>>();
    pew_gemm_kernel<<<dim3(L / 256, T / 64), 256, PEW_SMEM>>>(dw, db);
    hmma_sig_kernel<<<dim3(BB, L / 128, ZS), 256, HMMA_SMEM>>>();
    warp_kernel<<<(BB * L) / 256, 256>>>(x, out);
}

// round 8
// speedup vs baseline: 5.5729x; 1.4773x over previous
#include <cuda_runtime.h>
#include <cuda_fp16.h>
#include <math.h>
#include <stdint.h>

#define BB 16
#define T 4096
#define C 8
#define F 64
#define KW 11
#define PAD 5
#define L 4096
#define NTILE 32        // T/128 tiles (also L/128)

// ---- device scratch (no allocation allowed) ----
__device__ float g_h[BB * F * T];                              // conv+bn out [B][F][T]
__device__ __half g_sbf[(size_t)BB * NTILE * 128 * 64];        // S tiles [b][tile][t][f] SW128
__device__ __half g_wbf[NTILE * 128 * 64];                     // W hi tiles [ltile][l][f] SW128
__device__ __half g_wlo[NTILE * 128 * 64];                     // W lo tiles
__device__ __half g_pehi[NTILE * 128 * 64];                    // PE hi tiles [ttile][t][f] SW128
__device__ __half g_pelo[NTILE * 128 * 64];                    // PE lo tiles
__device__ float g_part2[(size_t)NTILE * BB * L];              // per-ttile partial shift sums

__device__ __forceinline__ uint32_t smem_u32(const void* p) {
    uint32_t a;
    asm("{ .reg .u64 t; cvta.to.shared.u64 t, %1; cvt.u32.u64 %0, t; }" : "=r"(a) : "l"(p));
    return a;
}
__host__ __device__ __forceinline__ uint32_t sw128(uint32_t off) {
    return off ^ ((off >> 3) & 0x70);
}

// ---------------------------------------------------------------------------
// K0a: PE -> fp16 hi/lo swizzled tiles [ttile][t][f]
// ---------------------------------------------------------------------------
__global__ void peprep_kernel() {
    int idx = blockIdx.x * 256 + threadIdx.x;      // F*T
    int f = idx >> 12, t = idx & (T - 1);
    float ts = powf(1e-4f, (float)(2 * (f >> 1)) / 64.0f);
    float ang = (float)t * ts;
    float v = (f & 1) ? cosf(ang) : sinf(ang);
    __half hi = __float2half(v);
    __half lo = __float2half(v - __half2float(hi));
    int tile = t >> 7, r = t & 127;
    uint32_t off = sw128(r * 128 + f * 2);
    *(__half*)((char*)g_pehi + (size_t)tile * 16384 + off) = hi;
    *(__half*)((char*)g_pelo + (size_t)tile * 16384 + off) = lo;
}

// ---------------------------------------------------------------------------
// K0b: W -> fp16 hi/lo swizzled tiles [ltile][l][f]
// ---------------------------------------------------------------------------
__global__ void wprep_kernel(const float* __restrict__ dw) {
    int idx = blockIdx.x * 256 + threadIdx.x;      // F*L
    int f = idx >> 12, l = idx & (L - 1);
    float v = dw[idx];
    __half hi = __float2half(v);
    __half lo = __float2half(v - __half2float(hi));
    int tile = l >> 7, r = l & 127;
    uint32_t off = sw128(r * 128 + f * 2);
    *(__half*)((char*)g_wbf + (size_t)tile * 16384 + off) = hi;
    *(__half*)((char*)g_wlo + (size_t)tile * 16384 + off) = lo;
}

// ---------------------------------------------------------------------------
// K1: Conv1D(SAME) + BatchNorm -> g_h [B][F][T]
// ---------------------------------------------------------------------------
#define CONV_TT 64
__global__ __launch_bounds__(256) void conv_bn_kernel(
    const float* __restrict__ x, const float* __restrict__ cw,
    const float* __restrict__ cb, const float* __restrict__ gamma,
    const float* __restrict__ beta, const float* __restrict__ mean,
    const float* __restrict__ var)
{
    __shared__ float xs[(CONV_TT + KW - 1) * 9];
    __shared__ float ws[KW * C * F];
    __shared__ float sc[F], bi[F];

    int b = blockIdx.y;
    int t0 = blockIdx.x * CONV_TT;
    int tid = threadIdx.x;

    for (int idx = tid; idx < (CONV_TT + KW - 1) * 9; idx += 256) {
        int i = idx / 9, c = idx % 9;
        float v = 0.f;
        int tg = t0 + i - PAD;
        if (c < 8 && tg >= 0 && tg < T) v = x[(b * T + tg) * C + c];
        xs[idx] = v;
    }
    for (int idx = tid; idx < KW * C * F; idx += 256) ws[idx] = cw[idx];
    if (tid < F) {
        float s = gamma[tid] / sqrtf(var[tid] + 1e-3f);
        sc[tid] = s;
        bi[tid] = (cb[tid] - mean[tid]) * s + beta[tid];
    }
    __syncthreads();

    int tx = tid & 31;
    int ty = tid >> 5;
    float acc0[8], acc1[8];
#pragma unroll
    for (int j = 0; j < 8; j++) { acc0[j] = 0.f; acc1[j] = 0.f; }

#pragma unroll
    for (int k = 0; k < KW; k++) {
#pragma unroll
        for (int c = 0; c < C; c++) {
            float x0 = xs[(tx * 2 + k) * 9 + c];
            float x1 = xs[(tx * 2 + 1 + k) * 9 + c];
            const float* wrow = &ws[(k * C + c) * F + ty * 8];
#pragma unroll
            for (int j = 0; j < 8; j++) {
                float w = wrow[j];
                acc0[j] += x0 * w;
                acc1[j] += x1 * w;
            }
        }
    }
#pragma unroll
    for (int j = 0; j < 8; j++) {
        int f = ty * 8 + j;
        float s = sc[f], o = bi[f];
        float2 v;
        v.x = acc0[j] * s + o;
        v.y = acc1[j] * s + o;
        *(float2*)&g_h[(size_t)(b * F + f) * T + t0 + tx * 2] = v;
    }
}

// ---------------------------------------------------------------------------
// K2: softmax over T, in-place fp32 into g_h
// ---------------------------------------------------------------------------
__global__ __launch_bounds__(256) void softmax_kernel()
{
    int r = blockIdx.x;            // b*F + f
    float* row = g_h + (size_t)r * T;
    int tid = threadIdx.x;

    float v[16];
#pragma unroll
    for (int i = 0; i < 16; i++) v[i] = row[i * 256 + tid];

    float m = v[0];
#pragma unroll
    for (int i = 1; i < 16; i++) m = fmaxf(m, v[i]);

    __shared__ float sm[8], ss[8];
#pragma unroll
    for (int o = 16; o > 0; o >>= 1) m = fmaxf(m, __shfl_xor_sync(~0u, m, o));
    if ((tid & 31) == 0) sm[tid >> 5] = m;
    __syncthreads();
    m = sm[0];
#pragma unroll
    for (int w = 1; w < 8; w++) m = fmaxf(m, sm[w]);

    float e[16];
    float lsum = 0.f;
#pragma unroll
    for (int i = 0; i < 16; i++) { e[i] = expf(v[i] - m); lsum += e[i]; }
#pragma unroll
    for (int o = 16; o > 0; o >>= 1) lsum += __shfl_xor_sync(~0u, lsum, o);
    if ((tid & 31) == 0) ss[tid >> 5] = lsum;
    __syncthreads();
    float total = 0.f;
#pragma unroll
    for (int w = 0; w < 8; w++) total += ss[w];

    float inv = 1.f / total;
#pragma unroll
    for (int i = 0; i < 16; i++) row[i * 256 + tid] = e[i] * inv;
}

// ---------------------------------------------------------------------------
// K2b: transpose S -> fp16 swizzled tiles g_sbf[b][tile][t][f]
// ---------------------------------------------------------------------------
__global__ __launch_bounds__(256) void strans_kernel()
{
    __shared__ float st[64][130];
    int b = blockIdx.y;
    int tile = blockIdx.x;
    int tid = threadIdx.x;
    const float* src = g_h + (size_t)b * F * T + tile * 128;

#pragma unroll
    for (int it = 0; it < 8; it++) {
        int e = tid + it * 256;        // f = e/32, t4 = e%32
        int f = e >> 5, t4 = e & 31;
        float4 v = *(const float4*)(src + (size_t)f * T + t4 * 4);
        st[f][t4 * 4 + 0] = v.x; st[f][t4 * 4 + 1] = v.y;
        st[f][t4 * 4 + 2] = v.z; st[f][t4 * 4 + 3] = v.w;
    }
    __syncthreads();

    char* dst = (char*)g_sbf + ((size_t)b * NTILE + tile) * 16384;
#pragma unroll
    for (int it = 0; it < 4; it++) {
        int e = tid + it * 256;        // t = e>>3, fc = e&7
        int t = e >> 3, fc = e & 7;
        __half tmp[8];
#pragma unroll
        for (int j = 0; j < 8; j++) tmp[j] = __float2half(st[fc * 8 + j][t]);
        *(float4*)(dst + sw128(t * 128 + fc * 16)) = *(float4*)tmp;
    }
}

// ---------------------------------------------------------------------------
// K3: fused HMMA: c_init = PEhi@Whi + PElo@Whi + PEhi@Wlo + bias (registers),
// then per b: c = c_init + S@W; sigmoid; t-sum -> g_part2[ttile][b][l]
// CTA = (ltile, ttile): 128 l x 128 t x 16 b; 256 threads = 8 warps (2tq x 4lq)
// ---------------------------------------------------------------------------
__device__ __forceinline__ void ldsm4(uint32_t* r, uint32_t addr) {
    asm volatile("ldmatrix.sync.aligned.m8n8.x4.shared.b16 {%0,%1,%2,%3}, [%4];"
                 : "=r"(r[0]), "=r"(r[1]), "=r"(r[2]), "=r"(r[3]) : "r"(addr));
}
__device__ __forceinline__ void mma16816(float* c, const uint32_t* a, const uint32_t* b) {
    asm volatile(
        "mma.sync.aligned.m16n8k16.row.col.f32.f16.f16.f32 "
        "{%0,%1,%2,%3}, {%4,%5,%6,%7}, {%8,%9}, {%0,%1,%2,%3};"
        : "+f"(c[0]), "+f"(c[1]), "+f"(c[2]), "+f"(c[3])
        : "r"(a[0]), "r"(a[1]), "r"(a[2]), "r"(a[3]), "r"(b[0]), "r"(b[1]));
}

extern __shared__ __align__(16) unsigned char g_smem[];

// smem regions (16KB each): R0=Whi  R1=Wlo (reduce scratch later)  R2/R3=S dbl buf
#define R0 0
#define R1 16384
#define R2 32768
#define R3 49152
#define HMMA_SMEM 65536

__global__ __launch_bounds__(256) void hmma_sig_kernel(const float* __restrict__ db)
{
    unsigned char* dsm = g_smem;
    int ltile = blockIdx.x, ttile = blockIdx.y;
    int l0 = ltile * 128;
    int tid = threadIdx.x, lane = tid & 31, w = tid >> 5;
    int tq = w >> 2, lq = w & 3;

    // load Whi, Wlo, PEhi(R2), PElo(R3)
    {
        const float4* s;
        float4* d;
        s = (const float4*)((const char*)g_wbf + (size_t)ltile * 16384);
        d = (float4*)(dsm + R0);
#pragma unroll
        for (int i = 0; i < 4; i++) d[tid + i * 256] = s[tid + i * 256];
        s = (const float4*)((const char*)g_wlo + (size_t)ltile * 16384);
        d = (float4*)(dsm + R1);
#pragma unroll
        for (int i = 0; i < 4; i++) d[tid + i * 256] = s[tid + i * 256];
        s = (const float4*)((const char*)g_pehi + (size_t)ttile * 16384);
        d = (float4*)(dsm + R2);
#pragma unroll
        for (int i = 0; i < 4; i++) d[tid + i * 256] = s[tid + i * 256];
        s = (const float4*)((const char*)g_pelo + (size_t)ttile * 16384);
        d = (float4*)(dsm + R3);
#pragma unroll
        for (int i = 0; i < 4; i++) d[tid + i * 256] = s[tid + i * 256];
    }
    __syncthreads();

    uint32_t base = smem_u32(dsm);

    // B fragments (W hi and lo)
    uint32_t Bfh[4][4][2], Bfl[4][4][2];
    {
        int grp = lane >> 3;
        int nrow = lq * 32 + ((grp & 2) << 2) + (lane & 7);
        int kh = grp & 1;
#pragma unroll
        for (int p = 0; p < 2; p++) {
#pragma unroll
            for (int k = 0; k < 4; k++) {
                uint32_t off = sw128((uint32_t)(nrow + p * 16) * 128 + k * 32 + kh * 16);
                uint32_t r[4];
                ldsm4(r, base + R0 + off);
                Bfh[2 * p][k][0] = r[0];     Bfh[2 * p][k][1] = r[1];
                Bfh[2 * p + 1][k][0] = r[2]; Bfh[2 * p + 1][k][1] = r[3];
                ldsm4(r, base + R1 + off);
                Bfl[2 * p][k][0] = r[0];     Bfl[2 * p][k][1] = r[1];
                Bfl[2 * p + 1][k][0] = r[2]; Bfl[2 * p + 1][k][1] = r[3];
            }
        }
    }

    int arow = lane & 15;
    int akh = lane >> 4;

    // bias values for this thread's 8 l columns
    float breg[8];
#pragma unroll
    for (int nf = 0; nf < 4; nf++) {
        breg[nf * 2 + 0] = db[l0 + lq * 32 + nf * 8 + (lane & 3) * 2 + 0];
        breg[nf * 2 + 1] = db[l0 + lq * 32 + nf * 8 + (lane & 3) * 2 + 1];
    }

    // c_init = PEhi@Whi + PElo@Whi + PEhi@Wlo + bias  (64 regs)
    float cinit[4][4][4];
#pragma unroll
    for (int tf = 0; tf < 4; tf++) {
        int row = tq * 64 + tf * 16 + arow;
        uint32_t Ah[4][4], Al[4][4];
#pragma unroll
        for (int k = 0; k < 4; k++) {
            uint32_t off = sw128((uint32_t)row * 128 + k * 32 + akh * 16);
            ldsm4(Ah[k], base + R2 + off);
            ldsm4(Al[k], base + R3 + off);
        }
        float c[4][4];
#pragma unroll
        for (int nf = 0; nf < 4; nf++)
#pragma unroll
            for (int q = 0; q < 4; q++) c[nf][q] = 0.f;
#pragma unroll
        for (int k = 0; k < 4; k++)
#pragma unroll
            for (int nf = 0; nf < 4; nf++) {
                mma16816(c[nf], Ah[k], Bfh[nf][k]);
                mma16816(c[nf], Al[k], Bfh[nf][k]);
                mma16816(c[nf], Ah[k], Bfl[nf][k]);
            }
#pragma unroll
        for (int nf = 0; nf < 4; nf++) {
            cinit[tf][nf][0] = c[nf][0] + breg[nf * 2 + 0];
            cinit[tf][nf][1] = c[nf][1] + breg[nf * 2 + 1];
            cinit[tf][nf][2] = c[nf][2] + breg[nf * 2 + 0];
            cinit[tf][nf][3] = c[nf][3] + breg[nf * 2 + 1];
        }
    }
    __syncthreads();   // done reading R2/R3 (PE tiles)

    // load S(b=0) into R2
    const char* sbase0 = (const char*)g_sbf + (size_t)ttile * 16384;
    {
        const float4* s = (const float4*)sbase0;   // b=0
        float4* d = (float4*)(dsm + R2);
#pragma unroll
        for (int i = 0; i < 4; i++) d[tid + i * 256] = s[tid + i * 256];
    }
    __syncthreads();

    float* red = (float*)(dsm + R1);

    for (int b = 0; b < BB; b++) {
        int cur = b & 1;
        uint32_t sA = base + (cur ? R3 : R2);

        // prefetch next S tile into registers
        float4 creg[4];
        if (b + 1 < BB) {
            const float4* s =
                (const float4*)(sbase0 + (size_t)(b + 1) * NTILE * 16384);
#pragma unroll
            for (int j = 0; j < 4; j++) creg[j] = s[tid + j * 256];
        }

        float dacc[8];
#pragma unroll
        for (int j = 0; j < 8; j++) dacc[j] = 0.f;

#pragma unroll
        for (int tf = 0; tf < 4; tf++) {
            int row = tq * 64 + tf * 16 + arow;
            uint32_t Af[4][4];
#pragma unroll
            for (int k = 0; k < 4; k++)
                ldsm4(Af[k], sA + sw128((uint32_t)row * 128 + k * 32 + akh * 16));

            float c[4][4];
#pragma unroll
            for (int nf = 0; nf < 4; nf++)
#pragma unroll
                for (int q = 0; q < 4; q++) c[nf][q] = cinit[tf][nf][q];
#pragma unroll
            for (int k = 0; k < 4; k++)
#pragma unroll
                for (int nf = 0; nf < 4; nf++) mma16816(c[nf], Af[k], Bfh[nf][k]);

            // accumulate 2*sigmoid(z); -1 corrected after loop
#pragma unroll
            for (int nf = 0; nf < 4; nf++) {
                float e;
                e = __expf(-c[nf][0]); dacc[nf * 2 + 0] += __fdividef(2.f, 1.f + e);
                e = __expf(-c[nf][1]); dacc[nf * 2 + 1] += __fdividef(2.f, 1.f + e);
                e = __expf(-c[nf][2]); dacc[nf * 2 + 0] += __fdividef(2.f, 1.f + e);
                e = __expf(-c[nf][3]); dacc[nf * 2 + 1] += __fdividef(2.f, 1.f + e);
            }
        }

        // each slot saw 4 tf * 2 = 8 elements of 2*sigmoid
#pragma unroll
        for (int j = 0; j < 8; j++) dacc[j] -= 8.f;

        // reduce over the 8 lanes sharing lane&3
#pragma unroll
        for (int o = 4; o < 32; o <<= 1)
#pragma unroll
            for (int j = 0; j < 8; j++) dacc[j] += __shfl_xor_sync(~0u, dacc[j], o);

        // store prefetched S tile
        if (b + 1 < BB) {
            float4* d = (float4*)(dsm + (cur ? R2 : R3));
#pragma unroll
            for (int j = 0; j < 4; j++) d[tid + j * 256] = creg[j];
        }

        if (lane < 4) {
#pragma unroll
            for (int nf = 0; nf < 4; nf++) {
                red[tq * 128 + lq * 32 + nf * 8 + lane * 2 + 0] = dacc[nf * 2 + 0];
                red[tq * 128 + lq * 32 + nf * 8 + lane * 2 + 1] = dacc[nf * 2 + 1];
            }
        }
        __syncthreads();
        if (tid < 128)
            g_part2[((size_t)ttile * BB + b) * L + l0 + tid] = red[tid] + red[128 + tid];
        __syncthreads();
    }
}

// ---------------------------------------------------------------------------
// K4: Gaussian RBF warp — sums 32 ttile partials, truncated window |d| <= 6
// ---------------------------------------------------------------------------
__global__ __launch_bounds__(256) void warp_kernel(
    const float* __restrict__ x, float* __restrict__ out)
{
    int gid = blockIdx.x * 256 + threadIdx.x;   // = b*L + l
    int b = gid >> 12;
    int l = gid & (L - 1);

    float shift = 0.f;
#pragma unroll
    for (int tt = 0; tt < NTILE; tt++) shift += g_part2[(size_t)tt * BB * L + gid];

    float scale = (float)T / (float)L;
    float s = ((float)(l + 1) + shift) * scale;

    const float INV_AMP = (float)(1.0 / 1.772637204826652);
    float acc[8];
#pragma unroll
    for (int c = 0; c < 8; c++) acc[c] = 0.f;

    int lo = (int)ceilf(s - 6.0f);  if (lo < 1) lo = 1;
    int hi = (int)floorf(s + 6.0f); if (hi > T) hi = T;

    const float* xb = x + (size_t)b * T * C;
    for (int t = lo; t <= hi; t++) {
        float dd = (float)t - s;
        float wgt = expf(-dd * dd) * INV_AMP;
        const float4* xr = (const float4*)&xb[(t - 1) * C];
        float4 p0 = xr[0], p1 = xr[1];
        acc[0] += wgt * p0.x; acc[1] += wgt * p0.y;
        acc[2] += wgt * p0.z; acc[3] += wgt * p0.w;
        acc[4] += wgt * p1.x; acc[5] += wgt * p1.y;
        acc[6] += wgt * p1.z; acc[7] += wgt * p1.w;
    }
    float4* o = (float4*)&out[(size_t)gid * C];
    float4 r0 = {acc[0], acc[1], acc[2], acc[3]};
    float4 r1 = {acc[4], acc[5], acc[6], acc[7]};
    o[0] = r0; o[1] = r1;
}

// ---------------------------------------------------------------------------
extern "C" void kernel_launch(void* const* d_in, const int* in_sizes, int n_in,
                              void* d_out, int out_size)
{
    const float* x     = (const float*)d_in[0];
    const float* cw    = (const float*)d_in[1];
    const float* cb    = (const float*)d_in[2];
    const float* gamma = (const float*)d_in[3];
    const float* beta  = (const float*)d_in[4];
    const float* mean  = (const float*)d_in[5];
    const float* var   = (const float*)d_in[6];
    const float* dw    = (const float*)d_in[7];
    const float* db    = (const float*)d_in[8];
    float* out = (float*)d_out;

    cudaFuncSetAttribute(hmma_sig_kernel,
                         cudaFuncAttributeMaxDynamicSharedMemorySize, HMMA_SMEM);

    peprep_kernel<<<(F * T) / 256, 256>>>();
    wprep_kernel<<<(F * L) / 256, 256>>>(dw);
    conv_bn_kernel<<<dim3(T / CONV_TT, BB), 256>>>(x, cw, cb, gamma, beta, mean, var);
    softmax_kernel<<<BB * F, 256>>>();
    strans_kernel<<<dim3(NTILE, BB), 256>>>();
    hmma_sig_kernel<<<dim3(NTILE, NTILE), 256, HMMA_SMEM>>>(db);
    warp_kernel<<<(BB * L) / 256, 256>>>(x, out);
}